// round 6
// baseline (speedup 1.0000x reference)
#include <cuda_runtime.h>
#include <math.h>
#include <stdint.h>

// LTCAttentionCell — round 6: int8 2-digit split GEMM on mma.sync.m16n8k32.s8
// (4096 MAC/instr = 2x fp16). a ~ sa*(ah + al/254) per-row scales.
// 3 terms: hi*hi (acc_hi), hi*lo + lo*hi (acc_mid, shared scale /254).
// Legacy path forced: harness ptxas targets sm_103 (no 'a'), so no tcgen05.

#define IN_DIM 128
#define HID    512
#define ATT    256
#define KTOT   896
#define BROWS  16384

#define BM 128
#define BN 64
#define NCH 28              // k32 chunks
#define NTH 256
#define STAGES 3
#define A_BYTES (128 * 64)  // 128 rows x [hi32|lo32]
#define B_BYTES (64 * 64)
#define STAGE_BYTES (A_BYTES + 3 * B_BYTES)   // 20480
#define SMEM_DYN (STAGES * STAGE_BYTES + 128)
#define WTAU_OFF ((size_t)1024 * 1792)

// ---------------- int8 scratch + scales ----------------
__device__ __align__(16) uint8_t g_comb8[(size_t)BROWS * 1792];           // [m][28*[hi32|lo32]]
__device__ __align__(16) uint8_t g_w8[(size_t)1024 * 1792 + (size_t)512 * 1024];
__device__ float g_sa[BROWS];
__device__ float g_sw[1536];   // 0..1023: W_gd rows; 1024..1535: W_tau rows

__device__ __forceinline__ uint32_t s2u(const void* p) {
    return (uint32_t)__cvta_generic_to_shared(p);
}
__device__ __forceinline__ void cp16(uint32_t dst, const void* src) {
    asm volatile("cp.async.cg.shared.global [%0], [%1], 16;" :: "r"(dst), "l"(src));
}
__device__ __forceinline__ void cp_commit() {
    asm volatile("cp.async.commit_group;" ::: "memory");
}
template<int N> __device__ __forceinline__ void cp_wait() {
    asm volatile("cp.async.wait_group %0;" :: "n"(N) : "memory");
}
__device__ __forceinline__ void ldm_x4(uint32_t* d, uint32_t addr) {
    asm volatile("ldmatrix.sync.aligned.m8n8.x4.shared.b16 {%0,%1,%2,%3}, [%4];"
                 : "=r"(d[0]), "=r"(d[1]), "=r"(d[2]), "=r"(d[3]) : "r"(addr));
}
__device__ __forceinline__ void mma_s8(int* c, const uint32_t* a, uint32_t b0, uint32_t b1) {
    asm volatile("mma.sync.aligned.m16n8k32.row.col.s32.s8.s8.s32 "
                 "{%0,%1,%2,%3}, {%4,%5,%6,%7}, {%8,%9}, {%0,%1,%2,%3};"
                 : "+r"(c[0]), "+r"(c[1]), "+r"(c[2]), "+r"(c[3])
                 : "r"(a[0]), "r"(a[1]), "r"(a[2]), "r"(a[3]), "r"(b0), "r"(b1));
}
__device__ __forceinline__ float softplus_f(float x) {
    return (x > 20.0f) ? x : log1pf(expf(x));
}

// rows of 64B = 4x16B chunks, swizzle ch ^ ((row>>1)&3): conflict-free for
// ldmatrix (odd/even rows alternate bank halves; same-parity rows get distinct chunks)
__device__ __forceinline__ uint32_t sw_addr(uint32_t base, int row, int ch) {
    return base + row * 64 + ((ch ^ ((row >> 1) & 3)) << 4);
}

// ---------------- quantization helpers ----------------
__device__ __forceinline__ uint32_t pk(int a, int b, int c, int d) {
    return (uint32_t)(a & 0xFF) | ((uint32_t)(b & 0xFF) << 8) |
           ((uint32_t)(c & 0xFF) << 16) | ((uint32_t)(d & 0xFF) << 24);
}
__device__ __forceinline__ void q4(float4 v, float inv, uint32_t& hi, uint32_t& lo) {
    float t0 = v.x * inv, t1 = v.y * inv, t2 = v.z * inv, t3 = v.w * inv;
    int h0 = __float2int_rn(t0), h1 = __float2int_rn(t1);
    int h2 = __float2int_rn(t2), h3 = __float2int_rn(t3);
    int l0 = __float2int_rn((t0 - (float)h0) * 254.f);
    int l1 = __float2int_rn((t1 - (float)h1) * 254.f);
    int l2 = __float2int_rn((t2 - (float)h2) * 254.f);
    int l3 = __float2int_rn((t3 - (float)h3) * 254.f);
    hi = pk(h0, h1, h2, h3);
    lo = pk(l0, l1, l2, l3);
}
__device__ __forceinline__ float wmax(float v) {
#pragma unroll
    for (int o = 16; o; o >>= 1) v = fmaxf(v, __shfl_xor_sync(0xFFFFFFFFu, v, o));
    return v;
}

// ---------------- pre-pass: combined rows ----------------
__global__ void __launch_bounds__(256)
prep_combined(const float* __restrict__ h_ltc, const float* __restrict__ x_t,
              const float* __restrict__ context)
{
    const int lane = threadIdx.x & 31;
    const int m = blockIdx.x * 8 + (threadIdx.x >> 5);
    float4 v[7];
    v[0] = *reinterpret_cast<const float4*>(&x_t[(size_t)m * IN_DIM + lane * 4]);
#pragma unroll
    for (int it = 1; it <= 4; ++it)
        v[it] = *reinterpret_cast<const float4*>(&h_ltc[(size_t)m * HID + (it - 1) * 128 + lane * 4]);
#pragma unroll
    for (int it = 5; it <= 6; ++it)
        v[it] = *reinterpret_cast<const float4*>(&context[(size_t)m * ATT + (it - 5) * 128 + lane * 4]);

    float amax = 1e-20f;
#pragma unroll
    for (int it = 0; it < 7; ++it) {
        amax = fmaxf(amax, fabsf(v[it].x)); amax = fmaxf(amax, fabsf(v[it].y));
        amax = fmaxf(amax, fabsf(v[it].z)); amax = fmaxf(amax, fabsf(v[it].w));
    }
    amax = wmax(amax);
    float sa = amax * (1.0f / 127.0f), inv = 127.0f / amax;
    if (lane == 0) g_sa[m] = sa;

#pragma unroll
    for (int it = 0; it < 7; ++it) {
        int k4 = it * 128 + lane * 4;
        int blk = k4 >> 5, off = k4 & 31;
        uint32_t hi, lo;
        q4(v[it], inv, hi, lo);
        uint8_t* base = &g_comb8[(size_t)m * 1792 + blk * 64 + off];
        *reinterpret_cast<uint32_t*>(base)      = hi;
        *reinterpret_cast<uint32_t*>(base + 32) = lo;
    }
}

// ---------------- pre-pass: weight rows ----------------
__global__ void __launch_bounds__(256)
prep_weights(const float* __restrict__ W_gd, const float* __restrict__ W_tau)
{
    const int lane = threadIdx.x & 31;
    const int row = blockIdx.x * 8 + (threadIdx.x >> 5);
    if (row < 1024) {
        float4 v[7];
#pragma unroll
        for (int it = 0; it < 7; ++it)
            v[it] = *reinterpret_cast<const float4*>(&W_gd[(size_t)row * KTOT + it * 128 + lane * 4]);
        float amax = 1e-20f;
#pragma unroll
        for (int it = 0; it < 7; ++it) {
            amax = fmaxf(amax, fabsf(v[it].x)); amax = fmaxf(amax, fabsf(v[it].y));
            amax = fmaxf(amax, fabsf(v[it].z)); amax = fmaxf(amax, fabsf(v[it].w));
        }
        amax = wmax(amax);
        float sa = amax * (1.0f / 127.0f), inv = 127.0f / amax;
        if (lane == 0) g_sw[row] = sa;
#pragma unroll
        for (int it = 0; it < 7; ++it) {
            int k4 = it * 128 + lane * 4;
            int blk = k4 >> 5, off = k4 & 31;
            uint32_t hi, lo;
            q4(v[it], inv, hi, lo);
            uint8_t* base = &g_w8[(size_t)row * 1792 + blk * 64 + off];
            *reinterpret_cast<uint32_t*>(base)      = hi;
            *reinterpret_cast<uint32_t*>(base + 32) = lo;
        }
    } else {
        int r2 = row - 1024;
        float4 v[4];
#pragma unroll
        for (int it = 0; it < 4; ++it)
            v[it] = *reinterpret_cast<const float4*>(&W_tau[(size_t)r2 * HID + it * 128 + lane * 4]);
        float amax = 1e-20f;
#pragma unroll
        for (int it = 0; it < 4; ++it) {
            amax = fmaxf(amax, fabsf(v[it].x)); amax = fmaxf(amax, fabsf(v[it].y));
            amax = fmaxf(amax, fabsf(v[it].z)); amax = fmaxf(amax, fabsf(v[it].w));
        }
        amax = wmax(amax);
        float sa = amax * (1.0f / 127.0f), inv = 127.0f / amax;
        if (lane == 0) g_sw[row] = sa;
#pragma unroll
        for (int it = 0; it < 4; ++it) {
            int k4 = it * 128 + lane * 4;
            int blk = k4 >> 5, off = k4 & 31;
            uint32_t hi, lo;
            q4(v[it], inv, hi, lo);
            uint8_t* base = &g_w8[WTAU_OFF + (size_t)r2 * 1024 + blk * 64 + off];
            *reinterpret_cast<uint32_t*>(base)      = hi;
            *reinterpret_cast<uint32_t*>(base + 32) = lo;
        }
    }
}

// ---------------- main kernel ----------------
__global__ void __launch_bounds__(NTH, 1)
ltc_s8_kernel(const float* __restrict__ h_ltc, const float* __restrict__ b_gd,
              const float* __restrict__ b_tau, const float* __restrict__ gleak,
              const float* __restrict__ cm, float* __restrict__ out)
{
    extern __shared__ char smem[];
    const uint32_t data = (s2u(smem) + 127) & ~127u;

    const int tid  = threadIdx.x;
    const int wid  = tid >> 5;
    const int lane = tid & 31;
    const int m0 = blockIdx.y * BM;
    const int n0 = blockIdx.x * BN;

    const int wm = (wid & 3) * 32;    // warp tile 32m x 32n
    const int wn = (wid >> 2) * 32;

    // ldmatrix lane decode (16B tiles over 64B rows)
    const int xa_row = ((lane >> 3) & 1) * 8 + (lane & 7);
    const int xa_ch  = (lane >> 4) & 1;
    const int xb_row = ((lane >> 4) & 1) * 8 + (lane & 7);
    const int xb_ch  = (lane >> 3) & 1;

    int ag_h[2][4][4] = {}, ag_m[2][4][4] = {};
    int ad_h[2][4][4] = {}, ad_m[2][4][4] = {};
    int at_h[2][4][4] = {}, at_m[2][4][4] = {};

    // loader coords
    const int ar = tid >> 2, ach = tid & 3;     // A: 2 iters (128 rows x 4 ch)
    const int br = tid >> 2, bch = tid & 3;     // B: 64 rows x 4 ch, one per matrix

    auto load_chunk = [&](int c) {
        uint32_t st = data + (c % STAGES) * STAGE_BYTES;
#pragma unroll
        for (int i = 0; i < 2; ++i) {
            int x = tid + i * 256;
            int r = x >> 2, ch = x & 3;
            cp16(sw_addr(st, r, ch),
                 g_comb8 + (size_t)(m0 + r) * 1792 + c * 64 + ch * 16);
        }
        uint32_t bo = sw_addr(0, br, bch);
        cp16(st + 8192  + bo, g_w8 + (size_t)(n0 + br) * 1792 + c * 64 + bch * 16);
        cp16(st + 12288 + bo, g_w8 + (size_t)(HID + n0 + br) * 1792 + c * 64 + bch * 16);
        if (c >= 4 && c < 20)
            cp16(st + 16384 + bo,
                 g_w8 + WTAU_OFF + (size_t)(n0 + br) * 1024 + (c - 4) * 64 + bch * 16);
        cp_commit();
    };

    load_chunk(0); load_chunk(1); load_chunk(2);

    for (int c = 0; c < NCH; ++c) {
        int rem = NCH - 1 - c;
        if (rem >= 2)      cp_wait<2>();
        else if (rem == 1) cp_wait<1>();
        else               cp_wait<0>();
        __syncthreads();

        const uint32_t st = data + (c % STAGES) * STAGE_BYTES;
        const bool tau_act = (c >= 4 && c < 20);

        uint32_t ah[2][4], al[2][4];
#pragma unroll
        for (int mb = 0; mb < 2; ++mb) {
            int row = wm + mb * 16 + xa_row;
            ldm_x4(ah[mb], sw_addr(st, row, xa_ch));
            ldm_x4(al[mb], sw_addr(st, row, xa_ch + 2));
        }

        // per matrix: Bh -> (Ah*Bh -> hi, Al*Bh -> mid); Bl (reuse regs) -> (Ah*Bl -> mid)
        auto do_mat = [&](uint32_t bbase, int h_acc[2][4][4], int m_acc[2][4][4]) {
            uint32_t b[2][4];
#pragma unroll
            for (int h = 0; h < 2; ++h)
                ldm_x4(b[h], sw_addr(bbase, wn + h * 16 + xb_row, xb_ch));
#pragma unroll
            for (int mb = 0; mb < 2; ++mb)
#pragma unroll
                for (int nb = 0; nb < 4; ++nb) {
                    uint32_t b0 = b[nb >> 1][(nb & 1) * 2], b1 = b[nb >> 1][(nb & 1) * 2 + 1];
                    mma_s8(h_acc[mb][nb], ah[mb], b0, b1);
                    mma_s8(m_acc[mb][nb], al[mb], b0, b1);
                }
#pragma unroll
            for (int h = 0; h < 2; ++h)
                ldm_x4(b[h], sw_addr(bbase, wn + h * 16 + xb_row, xb_ch + 2));
#pragma unroll
            for (int mb = 0; mb < 2; ++mb)
#pragma unroll
                for (int nb = 0; nb < 4; ++nb)
                    mma_s8(m_acc[mb][nb], ah[mb],
                           b[nb >> 1][(nb & 1) * 2], b[nb >> 1][(nb & 1) * 2 + 1]);
        };

        do_mat(st + 8192,  ag_h, ag_m);
        do_mat(st + 12288, ad_h, ad_m);
        if (tau_act) do_mat(st + 16384, at_h, at_m);

        __syncthreads();
        if (c + STAGES < NCH) load_chunk(c + STAGES);
    }

    // ---- fused epilogue ----
    const float INV254 = 1.0f / 254.0f;
    const int g  = lane >> 2;
    const int c2 = (lane & 3) * 2;
#pragma unroll
    for (int mb = 0; mb < 2; ++mb)
#pragma unroll
        for (int nb = 0; nb < 4; ++nb) {
            const int n = n0 + wn + nb * 8 + c2;
            const float sg0 = __ldg(&g_sw[n]),          sg1 = __ldg(&g_sw[n + 1]);
            const float sd0 = __ldg(&g_sw[HID + n]),    sd1 = __ldg(&g_sw[HID + n + 1]);
            const float st0 = __ldg(&g_sw[1024 + n]),   st1 = __ldg(&g_sw[1024 + n + 1]);
            const float bg0 = __ldg(&b_gd[n]),          bg1 = __ldg(&b_gd[n + 1]);
            const float bd0 = __ldg(&b_gd[n + HID]),    bd1 = __ldg(&b_gd[n + HID + 1]);
            const float bt0 = __ldg(&b_tau[n]),         bt1 = __ldg(&b_tau[n + 1]);
            const float dc0 = softplus_f(__ldg(&cm[n]))   + softplus_f(__ldg(&gleak[n]))   + 1e-6f;
            const float dc1 = softplus_f(__ldg(&cm[n+1])) + softplus_f(__ldg(&gleak[n+1])) + 1e-6f;
#pragma unroll
            for (int h = 0; h < 2; ++h) {
                const int m = m0 + wm + mb * 16 + h * 8 + g;
                const float sam = __ldg(&g_sa[m]);
                const float hl0 = __ldg(&h_ltc[(size_t)m * HID + n]);
                const float hl1 = __ldg(&h_ltc[(size_t)m * HID + n + 1]);

                float gate0 = ((float)ag_h[mb][nb][h*2+0] + (float)ag_m[mb][nb][h*2+0] * INV254) * (sam * sg0) + bg0;
                float gate1 = ((float)ag_h[mb][nb][h*2+1] + (float)ag_m[mb][nb][h*2+1] * INV254) * (sam * sg1) + bg1;
                float dyn0  = ((float)ad_h[mb][nb][h*2+0] + (float)ad_m[mb][nb][h*2+0] * INV254) * (sam * sd0) + bd0;
                float dyn1  = ((float)ad_h[mb][nb][h*2+1] + (float)ad_m[mb][nb][h*2+1] * INV254) * (sam * sd1) + bd1;
                float tau0  = softplus_f(((float)at_h[mb][nb][h*2+0] + (float)at_m[mb][nb][h*2+0] * INV254) * (sam * st0) + bt0);
                float tau1  = softplus_f(((float)at_h[mb][nb][h*2+1] + (float)at_m[mb][nb][h*2+1] * INV254) * (sam * st1) + bt1);

                float sig0 = 1.0f / (1.0f + expf(-gate0));
                float sig1 = 1.0f / (1.0f + expf(-gate1));
                float r0 = (sig0 * tanhf(dyn0) - hl0) / (tau0 + dc0);
                float r1 = (sig1 * tanhf(dyn1) - hl1) / (tau1 + dc1);

                float2 o; o.x = r0; o.y = r1;
                *reinterpret_cast<float2*>(&out[(size_t)m * HID + n]) = o;
            }
        }
}

extern "C" void kernel_launch(void* const* d_in, const int* in_sizes, int n_in,
                              void* d_out, int out_size)
{
    // input order: t, h_ltc, x_t, context, W_gd, b_gd, W_tau, b_tau, gleak, cm
    const float* h_ltc   = (const float*)d_in[1];
    const float* x_t     = (const float*)d_in[2];
    const float* context = (const float*)d_in[3];
    const float* W_gd    = (const float*)d_in[4];
    const float* b_gd    = (const float*)d_in[5];
    const float* W_tau   = (const float*)d_in[6];
    const float* b_tau   = (const float*)d_in[7];
    const float* gleak   = (const float*)d_in[8];
    const float* cm      = (const float*)d_in[9];
    float* out = (float*)d_out;

    cudaFuncSetAttribute(ltc_s8_kernel,
                         cudaFuncAttributeMaxDynamicSharedMemorySize, SMEM_DYN);

    prep_combined<<<2048, 256>>>(h_ltc, x_t, context);   // 16384 rows, 8/CTA
    prep_weights<<<192, 256>>>(W_gd, W_tau);             // 1536 rows, 8/CTA

    dim3 grid(HID / BN, BROWS / BM);   // (8, 128)
    ltc_s8_kernel<<<grid, NTH, SMEM_DYN>>>(h_ltc, b_gd, b_tau, gleak, cm, out);
}

// round 7
// speedup vs baseline: 3.8306x; 3.8306x over previous
#include <cuda_runtime.h>
#include <cuda_fp16.h>
#include <math.h>
#include <stdint.h>

// LTCAttentionCell — round 7: single-term fp16 HMMA (no split).
// R6 established: int8 mma.sync is ~4x slower on sm_103; fp16 HMMA is the
// fastest engine available (tcgen05 blocked: harness targets sm_103, not 103a).
// R4 established: B-only fp16 quantization error = 1.2e-4; adding A fp16
// quantization gives ~1.7e-4 total, well under the 1e-3 bound.
// Halves MMA instructions vs R4: predicted main kernel ~140us.

#define IN_DIM 128
#define HID    512
#define ATT    256
#define KTOT   896
#define BROWS  16384

#define BM 128
#define BN 64
#define KBLK 32
#define NCH (KTOT / KBLK)        // 28
#define NTH 256
#define STAGES 3
// stage: A 128 rows x 64B = 8K, Bg/Bd/Bt 64 rows x 64B = 4K each
#define STAGE_BYTES (8192 + 3 * 4096)
#define SMEM_DYN (STAGES * STAGE_BYTES + 128)

// ---------------- fp16 scratch ----------------
__device__ __half g_comb[(size_t)BROWS * KTOT];   // row-major [16384][896]
__device__ __half g_wgd [(size_t)1024  * KTOT];
__device__ __half g_wtau[(size_t)512   * HID];

__device__ __forceinline__ uint32_t s2u(const void* p) {
    return (uint32_t)__cvta_generic_to_shared(p);
}
__device__ __forceinline__ void cp16(uint32_t dst, const void* src) {
    asm volatile("cp.async.cg.shared.global [%0], [%1], 16;" :: "r"(dst), "l"(src));
}
__device__ __forceinline__ void cp_commit() {
    asm volatile("cp.async.commit_group;" ::: "memory");
}
template<int N> __device__ __forceinline__ void cp_wait() {
    asm volatile("cp.async.wait_group %0;" :: "n"(N) : "memory");
}
__device__ __forceinline__ void ldm_x4(uint32_t* d, uint32_t addr) {
    asm volatile("ldmatrix.sync.aligned.m8n8.x4.shared.b16 {%0,%1,%2,%3}, [%4];"
                 : "=r"(d[0]), "=r"(d[1]), "=r"(d[2]), "=r"(d[3]) : "r"(addr));
}
__device__ __forceinline__ void mma_f16(float* c, const uint32_t* a, uint32_t b0, uint32_t b1) {
    asm volatile("mma.sync.aligned.m16n8k16.row.col.f32.f16.f16.f32 "
                 "{%0,%1,%2,%3}, {%4,%5,%6,%7}, {%8,%9}, {%0,%1,%2,%3};"
                 : "+f"(c[0]), "+f"(c[1]), "+f"(c[2]), "+f"(c[3])
                 : "r"(a[0]), "r"(a[1]), "r"(a[2]), "r"(a[3]), "r"(b0), "r"(b1));
}
__device__ __forceinline__ float softplus_f(float x) {
    return (x > 20.0f) ? x : log1pf(expf(x));
}

// rows of 64B = 4x16B chunks, chunk swizzle ch ^ ((row>>1)&3)
__device__ __forceinline__ uint32_t sw_addr(uint32_t base, int row, int k) {
    int ch = k >> 3;
    return base + row * 64 + (((ch ^ ((row >> 1) & 3)) << 4) | ((k & 7) * 2));
}

// ---------------- pre-pass kernels ----------------
__global__ void __launch_bounds__(256)
prep_combined(const float* __restrict__ h_ltc, const float* __restrict__ x_t,
              const float* __restrict__ context)
{
    int idx = blockIdx.x * 256 + threadIdx.x;   // 16384 * 224
    int m = idx / 224;
    int j = (idx - m * 224) * 4;
    const float* src;
    if (j < IN_DIM)            src = x_t     + (size_t)m * IN_DIM + j;
    else if (j < IN_DIM + HID) src = h_ltc   + (size_t)m * HID    + (j - IN_DIM);
    else                       src = context + (size_t)m * ATT    + (j - IN_DIM - HID);
    float4 v = *reinterpret_cast<const float4*>(src);
    __half2 p0, p1;
    p0.x = __float2half_rn(v.x); p0.y = __float2half_rn(v.y);
    p1.x = __float2half_rn(v.z); p1.y = __float2half_rn(v.w);
    __half* dst = &g_comb[(size_t)m * KTOT + j];
    *reinterpret_cast<__half2*>(dst + 0) = p0;
    *reinterpret_cast<__half2*>(dst + 2) = p1;
}

__global__ void __launch_bounds__(256)
prep_weights(const float* __restrict__ W_gd, const float* __restrict__ W_tau)
{
    int idx = blockIdx.x * 256 + threadIdx.x;   // 229376 + 65536
    const float* src;
    __half* dst;
    if (idx < 229376) {
        int row = idx / 224;
        int j = (idx - row * 224) * 4;
        src = &W_gd[(size_t)row * KTOT + j];
        dst = &g_wgd[(size_t)row * KTOT + j];
    } else {
        int e = idx - 229376;
        int row = e >> 7;
        int j = (e & 127) * 4;
        src = &W_tau[(size_t)row * HID + j];
        dst = &g_wtau[(size_t)row * HID + j];
    }
    float4 v = *reinterpret_cast<const float4*>(src);
    __half2 p0, p1;
    p0.x = __float2half_rn(v.x); p0.y = __float2half_rn(v.y);
    p1.x = __float2half_rn(v.z); p1.y = __float2half_rn(v.w);
    *reinterpret_cast<__half2*>(dst + 0) = p0;
    *reinterpret_cast<__half2*>(dst + 2) = p1;
}

// ---------------- main kernel ----------------
__global__ void __launch_bounds__(NTH)
ltc_f16_kernel(const float* __restrict__ h_ltc, const float* __restrict__ b_gd,
               const float* __restrict__ b_tau, const float* __restrict__ gleak,
               const float* __restrict__ cm, float* __restrict__ out)
{
    extern __shared__ char smem[];
    const uint32_t data = (s2u(smem) + 127) & ~127u;

    const int tid  = threadIdx.x;
    const int wid  = tid >> 5;
    const int lane = tid & 31;
    const int m0 = blockIdx.y * BM;
    const int n0 = blockIdx.x * BN;

    const int wm = (wid & 3) * 32;    // warp tile 32m x 32n
    const int wn = (wid >> 2) * 32;

    const int a_row = ((lane >> 3) & 1) * 8 + (lane & 7);
    const int a_k   = ((lane >> 4) & 1) * 8;
    const int b_row = ((lane >> 4) & 1) * 8 + (lane & 7);
    const int b_k   = ((lane >> 3) & 1) * 8;

    float accg[2][4][4] = {}, accd[2][4][4] = {}, acct[2][4][4] = {};

    // loader coords: A 128 rows x 4 ch = 512 slots (2/thread); B 64x4 = 256 slots
    const int br = tid >> 2, bch = tid & 3;

    auto load_chunk = [&](int c) {
        uint32_t st = data + (c % STAGES) * STAGE_BYTES;
        const __half* pa = g_comb + (size_t)m0 * KTOT + c * 32;
#pragma unroll
        for (int i = 0; i < 2; ++i) {
            int x = tid + i * 256;
            int r = x >> 2, ch = x & 3;
            cp16(st + r * 64 + ((ch ^ ((r >> 1) & 3)) << 4),
                 pa + (size_t)r * KTOT + ch * 8);
        }
        uint32_t bo = br * 64 + ((bch ^ ((br >> 1) & 3)) << 4);
        cp16(st + 8192  + bo, g_wgd + (size_t)(n0 + br) * KTOT + c * 32 + bch * 8);
        cp16(st + 12288 + bo, g_wgd + (size_t)(HID + n0 + br) * KTOT + c * 32 + bch * 8);
        if (c >= 4 && c < 20)
            cp16(st + 16384 + bo,
                 g_wtau + (size_t)(n0 + br) * HID + (c - 4) * 32 + bch * 8);
        cp_commit();
    };

    load_chunk(0); load_chunk(1); load_chunk(2);

    for (int c = 0; c < NCH; ++c) {
        int rem = NCH - 1 - c;
        if (rem >= 2)      cp_wait<2>();
        else if (rem == 1) cp_wait<1>();
        else               cp_wait<0>();
        __syncthreads();

        const uint32_t st = data + (c % STAGES) * STAGE_BYTES;
        const bool tau_act = (c >= 4 && c < 20);

#pragma unroll
        for (int ks = 0; ks < KBLK; ks += 16) {
            uint32_t a[2][4];
#pragma unroll
            for (int mb = 0; mb < 2; ++mb)
                ldm_x4(a[mb], sw_addr(st, wm + mb * 16 + a_row, ks + a_k));

            auto do_mat = [&](uint32_t bbase, float acc[2][4][4]) {
                uint32_t b[2][4];
#pragma unroll
                for (int h = 0; h < 2; ++h)
                    ldm_x4(b[h], sw_addr(bbase, wn + h * 16 + b_row, ks + b_k));
#pragma unroll
                for (int mb = 0; mb < 2; ++mb)
#pragma unroll
                    for (int nb = 0; nb < 4; ++nb)
                        mma_f16(acc[mb][nb], a[mb],
                                b[nb >> 1][(nb & 1) * 2], b[nb >> 1][(nb & 1) * 2 + 1]);
            };
            do_mat(st + 8192,  accg);
            do_mat(st + 12288, accd);
            if (tau_act) do_mat(st + 16384, acct);
        }
        __syncthreads();
        if (c + STAGES < NCH) load_chunk(c + STAGES);
    }

    // ---- fused epilogue ----
    const int g  = lane >> 2;
    const int c2 = (lane & 3) * 2;
#pragma unroll
    for (int mb = 0; mb < 2; ++mb)
#pragma unroll
        for (int nb = 0; nb < 4; ++nb) {
            const int n = n0 + wn + nb * 8 + c2;
            const float bg0 = __ldg(&b_gd[n]),        bg1 = __ldg(&b_gd[n + 1]);
            const float bd0 = __ldg(&b_gd[n + HID]),  bd1 = __ldg(&b_gd[n + HID + 1]);
            const float bt0 = __ldg(&b_tau[n]),       bt1 = __ldg(&b_tau[n + 1]);
            const float dc0 = softplus_f(__ldg(&cm[n]))   + softplus_f(__ldg(&gleak[n]))   + 1e-6f;
            const float dc1 = softplus_f(__ldg(&cm[n+1])) + softplus_f(__ldg(&gleak[n+1])) + 1e-6f;
#pragma unroll
            for (int h = 0; h < 2; ++h) {
                const int m = m0 + wm + mb * 16 + h * 8 + g;
                const float hl0 = __ldg(&h_ltc[(size_t)m * HID + n]);
                const float hl1 = __ldg(&h_ltc[(size_t)m * HID + n + 1]);

                float gate0 = accg[mb][nb][h * 2 + 0] + bg0;
                float gate1 = accg[mb][nb][h * 2 + 1] + bg1;
                float dyn0  = accd[mb][nb][h * 2 + 0] + bd0;
                float dyn1  = accd[mb][nb][h * 2 + 1] + bd1;
                float tau0  = softplus_f(acct[mb][nb][h * 2 + 0] + bt0);
                float tau1  = softplus_f(acct[mb][nb][h * 2 + 1] + bt1);

                float sig0 = 1.0f / (1.0f + expf(-gate0));
                float sig1 = 1.0f / (1.0f + expf(-gate1));
                float r0 = (sig0 * tanhf(dyn0) - hl0) / (tau0 + dc0);
                float r1 = (sig1 * tanhf(dyn1) - hl1) / (tau1 + dc1);

                float2 o; o.x = r0; o.y = r1;
                *reinterpret_cast<float2*>(&out[(size_t)m * HID + n]) = o;
            }
        }
}

extern "C" void kernel_launch(void* const* d_in, const int* in_sizes, int n_in,
                              void* d_out, int out_size)
{
    // input order: t, h_ltc, x_t, context, W_gd, b_gd, W_tau, b_tau, gleak, cm
    const float* h_ltc   = (const float*)d_in[1];
    const float* x_t     = (const float*)d_in[2];
    const float* context = (const float*)d_in[3];
    const float* W_gd    = (const float*)d_in[4];
    const float* b_gd    = (const float*)d_in[5];
    const float* W_tau   = (const float*)d_in[6];
    const float* b_tau   = (const float*)d_in[7];
    const float* gleak   = (const float*)d_in[8];
    const float* cm      = (const float*)d_in[9];
    float* out = (float*)d_out;

    cudaFuncSetAttribute(ltc_f16_kernel,
                         cudaFuncAttributeMaxDynamicSharedMemorySize, SMEM_DYN);

    prep_combined<<<14336, 256>>>(h_ltc, x_t, context);
    prep_weights<<<1152, 256>>>(W_gd, W_tau);

    dim3 grid(HID / BN, BROWS / BM);   // (8, 128)
    ltc_f16_kernel<<<grid, NTH, SMEM_DYN>>>(h_ltc, b_gd, b_tau, gleak, cm, out);
}

// round 8
// speedup vs baseline: 4.4070x; 1.1505x over previous
#include <cuda_runtime.h>
#include <cuda_fp16.h>
#include <math.h>
#include <stdint.h>

// LTCAttentionCell — round 8: single-term fp16 HMMA, 16 warps (4/SMSP) to hide
// LDSM->MMA latency (R7 ran at 63% of issue ceiling with 8 warps), single
// __syncthreads per chunk (2-ahead prefetch), fused prep kernel.

#define IN_DIM 128
#define HID    512
#define ATT    256
#define KTOT   896
#define BROWS  16384

#define BM 128
#define BN 64
#define KBLK 32
#define NCH (KTOT / KBLK)        // 28
#define NTH 512
#define STAGES 3
// stage: A 128 rows x 64B = 8K, Bg/Bd/Bt 64 rows x 64B = 4K each
#define STAGE_BYTES (8192 + 3 * 4096)
#define SMEM_DYN (STAGES * STAGE_BYTES + 128)

// ---------------- fp16 scratch ----------------
__device__ __half g_comb[(size_t)BROWS * KTOT];
__device__ __half g_wgd [(size_t)1024  * KTOT];
__device__ __half g_wtau[(size_t)512   * HID];

__device__ __forceinline__ uint32_t s2u(const void* p) {
    return (uint32_t)__cvta_generic_to_shared(p);
}
__device__ __forceinline__ void cp16(uint32_t dst, const void* src) {
    asm volatile("cp.async.cg.shared.global [%0], [%1], 16;" :: "r"(dst), "l"(src));
}
__device__ __forceinline__ void cp_commit() {
    asm volatile("cp.async.commit_group;" ::: "memory");
}
template<int N> __device__ __forceinline__ void cp_wait() {
    asm volatile("cp.async.wait_group %0;" :: "n"(N) : "memory");
}
__device__ __forceinline__ void ldm_x4(uint32_t* d, uint32_t addr) {
    asm volatile("ldmatrix.sync.aligned.m8n8.x4.shared.b16 {%0,%1,%2,%3}, [%4];"
                 : "=r"(d[0]), "=r"(d[1]), "=r"(d[2]), "=r"(d[3]) : "r"(addr));
}
__device__ __forceinline__ void mma_f16(float* c, const uint32_t* a, uint32_t b0, uint32_t b1) {
    asm volatile("mma.sync.aligned.m16n8k16.row.col.f32.f16.f16.f32 "
                 "{%0,%1,%2,%3}, {%4,%5,%6,%7}, {%8,%9}, {%0,%1,%2,%3};"
                 : "+f"(c[0]), "+f"(c[1]), "+f"(c[2]), "+f"(c[3])
                 : "r"(a[0]), "r"(a[1]), "r"(a[2]), "r"(a[3]), "r"(b0), "r"(b1));
}
__device__ __forceinline__ float softplus_f(float x) {
    return (x > 20.0f) ? x : log1pf(expf(x));
}

// rows of 64B = 4x16B chunks, chunk swizzle ch ^ ((row>>1)&3)
__device__ __forceinline__ uint32_t sw_addr(uint32_t base, int row, int k) {
    int ch = k >> 3;
    return base + row * 64 + (((ch ^ ((row >> 1) & 3)) << 4) | ((k & 7) * 2));
}

// ---------------- fused pre-pass ----------------
// blocks [0, 14336): combined rows; blocks [14336, 15488): weights
__global__ void __launch_bounds__(256)
prep_all(const float* __restrict__ h_ltc, const float* __restrict__ x_t,
         const float* __restrict__ context, const float* __restrict__ W_gd,
         const float* __restrict__ W_tau)
{
    const float* src;
    __half* dst;
    if (blockIdx.x < 14336) {
        int idx = blockIdx.x * 256 + threadIdx.x;   // 16384 * 224
        int m = idx / 224;
        int j = (idx - m * 224) * 4;
        if (j < IN_DIM)            src = x_t     + (size_t)m * IN_DIM + j;
        else if (j < IN_DIM + HID) src = h_ltc   + (size_t)m * HID    + (j - IN_DIM);
        else                       src = context + (size_t)m * ATT    + (j - IN_DIM - HID);
        dst = &g_comb[(size_t)m * KTOT + j];
    } else {
        int idx = (blockIdx.x - 14336) * 256 + threadIdx.x;  // 229376 + 65536
        if (idx < 229376) {
            int row = idx / 224;
            int j = (idx - row * 224) * 4;
            src = &W_gd[(size_t)row * KTOT + j];
            dst = &g_wgd[(size_t)row * KTOT + j];
        } else {
            int e = idx - 229376;
            int row = e >> 7;
            int j = (e & 127) * 4;
            src = &W_tau[(size_t)row * HID + j];
            dst = &g_wtau[(size_t)row * HID + j];
        }
    }
    float4 v = *reinterpret_cast<const float4*>(src);
    __half2 p0, p1;
    p0.x = __float2half_rn(v.x); p0.y = __float2half_rn(v.y);
    p1.x = __float2half_rn(v.z); p1.y = __float2half_rn(v.w);
    *reinterpret_cast<__half2*>(dst + 0) = p0;
    *reinterpret_cast<__half2*>(dst + 2) = p1;
}

// ---------------- main kernel ----------------
__global__ void __launch_bounds__(NTH, 1)
ltc_f16_kernel(const float* __restrict__ h_ltc, const float* __restrict__ b_gd,
               const float* __restrict__ b_tau, const float* __restrict__ gleak,
               const float* __restrict__ cm, float* __restrict__ out)
{
    extern __shared__ char smem[];
    const uint32_t data = (s2u(smem) + 127) & ~127u;

    const int tid  = threadIdx.x;
    const int wid  = tid >> 5;
    const int lane = tid & 31;
    const int m0 = blockIdx.y * BM;
    const int n0 = blockIdx.x * BN;

    // 16 warps: 4 m-warps x 4 n-warps; warp tile 32m x 16n
    const int wm = (wid & 3) * 32;
    const int wn = (wid >> 2) * 16;

    const int a_row = ((lane >> 3) & 1) * 8 + (lane & 7);
    const int a_k   = ((lane >> 4) & 1) * 8;
    const int b_row = ((lane >> 4) & 1) * 8 + (lane & 7);
    const int b_k   = ((lane >> 3) & 1) * 8;

    float accg[2][2][4] = {}, accd[2][2][4] = {}, acct[2][2][4] = {};

    // loaders: A 128 rows x 4 ch = 512 slots -> 1/thread
    const int ar = tid >> 2, ach = tid & 3;
    // B: slot s = tid & 255 -> row s>>2, chunk s&3; low half Bg(+Bt), high half Bd
    const int br = (tid & 255) >> 2, bch = tid & 3;
    const bool lowhalf = tid < 256;

    auto load_chunk = [&](int c) {
        uint32_t st = data + (c % STAGES) * STAGE_BYTES;
        cp16(st + ar * 64 + ((ach ^ ((ar >> 1) & 3)) << 4),
             g_comb + (size_t)(m0 + ar) * KTOT + c * 32 + ach * 8);
        uint32_t bo = br * 64 + ((bch ^ ((br >> 1) & 3)) << 4);
        if (lowhalf) {
            cp16(st + 8192 + bo,
                 g_wgd + (size_t)(n0 + br) * KTOT + c * 32 + bch * 8);
            if (c >= 4 && c < 20)
                cp16(st + 16384 + bo,
                     g_wtau + (size_t)(n0 + br) * HID + (c - 4) * 32 + bch * 8);
        } else {
            cp16(st + 12288 + bo,
                 g_wgd + (size_t)(HID + n0 + br) * KTOT + c * 32 + bch * 8);
        }
        cp_commit();
    };

    load_chunk(0); load_chunk(1);

    for (int c = 0; c < NCH; ++c) {
        if (c + 1 < NCH) cp_wait<1>();
        else             cp_wait<0>();
        __syncthreads();
        // prefetch chunk c+2 -> stage (c+2)%3 == (c-1)%3, consumed in iter c-1,
        // all warps past this barrier => safe with a single sync per iteration.
        if (c + 2 < NCH) load_chunk(c + 2);

        const uint32_t st = data + (c % STAGES) * STAGE_BYTES;
        const bool tau_act = (c >= 4 && c < 20);

#pragma unroll
        for (int ks = 0; ks < KBLK; ks += 16) {
            uint32_t a[2][4];
#pragma unroll
            for (int mb = 0; mb < 2; ++mb)
                ldm_x4(a[mb], sw_addr(st, wm + mb * 16 + a_row, ks + a_k));

            uint32_t bg[4], bd[4], bt[4];
            ldm_x4(bg, sw_addr(st + 8192,  wn + b_row, ks + b_k));
            ldm_x4(bd, sw_addr(st + 12288, wn + b_row, ks + b_k));
            if (tau_act)
                ldm_x4(bt, sw_addr(st + 16384, wn + b_row, ks + b_k));

#pragma unroll
            for (int mb = 0; mb < 2; ++mb)
#pragma unroll
                for (int nb = 0; nb < 2; ++nb) {
                    mma_f16(accg[mb][nb], a[mb], bg[nb * 2], bg[nb * 2 + 1]);
                    mma_f16(accd[mb][nb], a[mb], bd[nb * 2], bd[nb * 2 + 1]);
                }
            if (tau_act) {
#pragma unroll
                for (int mb = 0; mb < 2; ++mb)
#pragma unroll
                    for (int nb = 0; nb < 2; ++nb)
                        mma_f16(acct[mb][nb], a[mb], bt[nb * 2], bt[nb * 2 + 1]);
            }
        }
    }

    // ---- fused epilogue (warp tile 32x16) ----
    const int g  = lane >> 2;
    const int c2 = (lane & 3) * 2;
#pragma unroll
    for (int mb = 0; mb < 2; ++mb)
#pragma unroll
        for (int nb = 0; nb < 2; ++nb) {
            const int n = n0 + wn + nb * 8 + c2;
            const float bg0 = __ldg(&b_gd[n]),        bg1 = __ldg(&b_gd[n + 1]);
            const float bd0 = __ldg(&b_gd[n + HID]),  bd1 = __ldg(&b_gd[n + HID + 1]);
            const float bt0 = __ldg(&b_tau[n]),       bt1 = __ldg(&b_tau[n + 1]);
            const float dc0 = softplus_f(__ldg(&cm[n]))   + softplus_f(__ldg(&gleak[n]))   + 1e-6f;
            const float dc1 = softplus_f(__ldg(&cm[n+1])) + softplus_f(__ldg(&gleak[n+1])) + 1e-6f;
#pragma unroll
            for (int h = 0; h < 2; ++h) {
                const int m = m0 + wm + mb * 16 + h * 8 + g;
                const float hl0 = __ldg(&h_ltc[(size_t)m * HID + n]);
                const float hl1 = __ldg(&h_ltc[(size_t)m * HID + n + 1]);

                float gate0 = accg[mb][nb][h * 2 + 0] + bg0;
                float gate1 = accg[mb][nb][h * 2 + 1] + bg1;
                float dyn0  = accd[mb][nb][h * 2 + 0] + bd0;
                float dyn1  = accd[mb][nb][h * 2 + 1] + bd1;
                float tau0  = softplus_f(acct[mb][nb][h * 2 + 0] + bt0);
                float tau1  = softplus_f(acct[mb][nb][h * 2 + 1] + bt1);

                float sig0 = 1.0f / (1.0f + expf(-gate0));
                float sig1 = 1.0f / (1.0f + expf(-gate1));
                float r0 = (sig0 * tanhf(dyn0) - hl0) / (tau0 + dc0);
                float r1 = (sig1 * tanhf(dyn1) - hl1) / (tau1 + dc1);

                float2 o; o.x = r0; o.y = r1;
                *reinterpret_cast<float2*>(&out[(size_t)m * HID + n]) = o;
            }
        }
}

extern "C" void kernel_launch(void* const* d_in, const int* in_sizes, int n_in,
                              void* d_out, int out_size)
{
    // input order: t, h_ltc, x_t, context, W_gd, b_gd, W_tau, b_tau, gleak, cm
    const float* h_ltc   = (const float*)d_in[1];
    const float* x_t     = (const float*)d_in[2];
    const float* context = (const float*)d_in[3];
    const float* W_gd    = (const float*)d_in[4];
    const float* b_gd    = (const float*)d_in[5];
    const float* W_tau   = (const float*)d_in[6];
    const float* b_tau   = (const float*)d_in[7];
    const float* gleak   = (const float*)d_in[8];
    const float* cm      = (const float*)d_in[9];
    float* out = (float*)d_out;

    cudaFuncSetAttribute(ltc_f16_kernel,
                         cudaFuncAttributeMaxDynamicSharedMemorySize, SMEM_DYN);

    prep_all<<<15488, 256>>>(h_ltc, x_t, context, W_gd, W_tau);

    dim3 grid(HID / BN, BROWS / BM);   // (8, 128)
    ltc_f16_kernel<<<grid, NTH, SMEM_DYN>>>(h_ltc, b_gd, b_tau, gleak, cm, out);
}

// round 9
// speedup vs baseline: 4.9274x; 1.1181x over previous
#include <cuda_runtime.h>
#include <cuda_fp16.h>
#include <math.h>
#include <stdint.h>

// LTCAttentionCell — round 9: R8 (fp16 HMMA, 16 warps, 1 sync/chunk) with all
// LDSM/cp.async addressing hoisted: 3-way unrolled chunk loop gives compile-time
// stage bases; swizzled offsets precomputed once (R8 burned 25.5% of issue on ALU).

#define IN_DIM 128
#define HID    512
#define ATT    256
#define KTOT   896
#define BROWS  16384

#define BM 128
#define BN 64
#define KBLK 32
#define NCH (KTOT / KBLK)        // 28
#define NTH 512
#define STAGES 3
#define STAGE_BYTES (8192 + 3 * 4096)
#define SMEM_DYN (STAGES * STAGE_BYTES + 128)

__device__ __half g_comb[(size_t)BROWS * KTOT];
__device__ __half g_wgd [(size_t)1024  * KTOT];
__device__ __half g_wtau[(size_t)512   * HID];

__device__ __forceinline__ uint32_t s2u(const void* p) {
    return (uint32_t)__cvta_generic_to_shared(p);
}
__device__ __forceinline__ void cp16(uint32_t dst, const void* src) {
    asm volatile("cp.async.cg.shared.global [%0], [%1], 16;" :: "r"(dst), "l"(src));
}
__device__ __forceinline__ void cp_commit() {
    asm volatile("cp.async.commit_group;" ::: "memory");
}
template<int N> __device__ __forceinline__ void cp_wait() {
    asm volatile("cp.async.wait_group %0;" :: "n"(N) : "memory");
}
__device__ __forceinline__ void ldm_x4(uint32_t* d, uint32_t addr) {
    asm volatile("ldmatrix.sync.aligned.m8n8.x4.shared.b16 {%0,%1,%2,%3}, [%4];"
                 : "=r"(d[0]), "=r"(d[1]), "=r"(d[2]), "=r"(d[3]) : "r"(addr));
}
__device__ __forceinline__ void mma_f16(float* c, const uint32_t* a, uint32_t b0, uint32_t b1) {
    asm volatile("mma.sync.aligned.m16n8k16.row.col.f32.f16.f16.f32 "
                 "{%0,%1,%2,%3}, {%4,%5,%6,%7}, {%8,%9}, {%0,%1,%2,%3};"
                 : "+f"(c[0]), "+f"(c[1]), "+f"(c[2]), "+f"(c[3])
                 : "r"(a[0]), "r"(a[1]), "r"(a[2]), "r"(a[3]), "r"(b0), "r"(b1));
}
__device__ __forceinline__ float softplus_f(float x) {
    return (x > 20.0f) ? x : log1pf(expf(x));
}

// rows of 64B = 4x16B chunks, chunk swizzle ch ^ ((row>>1)&3)
__device__ __forceinline__ uint32_t sw_off(int row, int k) {
    int ch = k >> 3;
    return row * 64 + (((ch ^ ((row >> 1) & 3)) << 4) | ((k & 7) * 2));
}

// ---------------- fused pre-pass ----------------
__global__ void __launch_bounds__(256)
prep_all(const float* __restrict__ h_ltc, const float* __restrict__ x_t,
         const float* __restrict__ context, const float* __restrict__ W_gd,
         const float* __restrict__ W_tau)
{
    const float* src;
    __half* dst;
    if (blockIdx.x < 14336) {
        int idx = blockIdx.x * 256 + threadIdx.x;   // 16384 * 224
        int m = idx / 224;
        int j = (idx - m * 224) * 4;
        if (j < IN_DIM)            src = x_t     + (size_t)m * IN_DIM + j;
        else if (j < IN_DIM + HID) src = h_ltc   + (size_t)m * HID    + (j - IN_DIM);
        else                       src = context + (size_t)m * ATT    + (j - IN_DIM - HID);
        dst = &g_comb[(size_t)m * KTOT + j];
    } else {
        int idx = (blockIdx.x - 14336) * 256 + threadIdx.x;  // 229376 + 65536
        if (idx < 229376) {
            int row = idx / 224;
            int j = (idx - row * 224) * 4;
            src = &W_gd[(size_t)row * KTOT + j];
            dst = &g_wgd[(size_t)row * KTOT + j];
        } else {
            int e = idx - 229376;
            int row = e >> 7;
            int j = (e & 127) * 4;
            src = &W_tau[(size_t)row * HID + j];
            dst = &g_wtau[(size_t)row * HID + j];
        }
    }
    float4 v = *reinterpret_cast<const float4*>(src);
    __half2 p0, p1;
    p0.x = __float2half_rn(v.x); p0.y = __float2half_rn(v.y);
    p1.x = __float2half_rn(v.z); p1.y = __float2half_rn(v.w);
    *reinterpret_cast<__half2*>(dst + 0) = p0;
    *reinterpret_cast<__half2*>(dst + 2) = p1;
}

// ---------------- main kernel ----------------
__global__ void __launch_bounds__(NTH, 1)
ltc_f16_kernel(const float* __restrict__ h_ltc, const float* __restrict__ b_gd,
               const float* __restrict__ b_tau, const float* __restrict__ gleak,
               const float* __restrict__ cm, float* __restrict__ out)
{
    extern __shared__ char smem[];
    const uint32_t data = (s2u(smem) + 127) & ~127u;

    const int tid  = threadIdx.x;
    const int wid  = tid >> 5;
    const int lane = tid & 31;
    const int m0 = blockIdx.y * BM;
    const int n0 = blockIdx.x * BN;

    const int wm = (wid & 3) * 32;
    const int wn = (wid >> 2) * 16;

    const int a_row = ((lane >> 3) & 1) * 8 + (lane & 7);
    const int a_k   = ((lane >> 4) & 1) * 8;
    const int b_row = ((lane >> 4) & 1) * 8 + (lane & 7);
    const int b_k   = ((lane >> 3) & 1) * 8;

    // -------- precomputed LDSM offsets (stage-relative) --------
    uint32_t aoff[2][2], bgof[2], bdof[2], btof[2];
#pragma unroll
    for (int ks = 0; ks < 2; ++ks) {
#pragma unroll
        for (int mb = 0; mb < 2; ++mb)
            aoff[mb][ks] = sw_off(wm + mb * 16 + a_row, ks * 16 + a_k);
        bgof[ks] = 8192  + sw_off(wn + b_row, ks * 16 + b_k);
        bdof[ks] = 12288 + sw_off(wn + b_row, ks * 16 + b_k);
        btof[ks] = 16384 + sw_off(wn + b_row, ks * 16 + b_k);
    }

    // -------- precomputed loader addressing --------
    const int ar = tid >> 2, ach = tid & 3;
    const int br = (tid & 255) >> 2, bch = tid & 3;
    const bool lowhalf = tid < 256;
    const uint32_t dA = ar * 64 + ((ach ^ ((ar >> 1) & 3)) << 4);
    const uint32_t dB = br * 64 + ((bch ^ ((br >> 1) & 3)) << 4);
    const __half* srcA = g_comb + (size_t)(m0 + ar) * KTOT + ach * 8;
    const __half* srcG = g_wgd  + (size_t)(n0 + br) * KTOT + bch * 8;
    const __half* srcD = g_wgd  + (size_t)(HID + n0 + br) * KTOT + bch * 8;
    const __half* srcT = g_wtau + (size_t)(n0 + br) * HID + bch * 8;

    float accg[2][2][4] = {}, accd[2][2][4] = {}, acct[2][2][4] = {};

    auto load_chunk = [&](int c, uint32_t st) {
        cp16(st + dA, srcA + c * 32);
        if (lowhalf) {
            cp16(st + 8192 + dB, srcG + c * 32);
            if (c >= 4 && c < 20)
                cp16(st + 16384 + dB, srcT + (c - 4) * 32);
        } else {
            cp16(st + 12288 + dB, srcD + c * 32);
        }
        cp_commit();
    };

    auto compute = [&](uint32_t st, bool tau_act) {
#pragma unroll
        for (int ks = 0; ks < 2; ++ks) {
            uint32_t a[2][4];
            ldm_x4(a[0], st + aoff[0][ks]);
            ldm_x4(a[1], st + aoff[1][ks]);
            uint32_t bg[4], bd[4], bt[4];
            ldm_x4(bg, st + bgof[ks]);
            ldm_x4(bd, st + bdof[ks]);
            if (tau_act) ldm_x4(bt, st + btof[ks]);
#pragma unroll
            for (int mb = 0; mb < 2; ++mb)
#pragma unroll
                for (int nb = 0; nb < 2; ++nb) {
                    mma_f16(accg[mb][nb], a[mb], bg[nb * 2], bg[nb * 2 + 1]);
                    mma_f16(accd[mb][nb], a[mb], bd[nb * 2], bd[nb * 2 + 1]);
                }
            if (tau_act) {
#pragma unroll
                for (int mb = 0; mb < 2; ++mb)
#pragma unroll
                    for (int nb = 0; nb < 2; ++nb)
                        mma_f16(acct[mb][nb], a[mb], bt[nb * 2], bt[nb * 2 + 1]);
            }
        }
    };

    const uint32_t st0 = data;
    const uint32_t st1 = data + STAGE_BYTES;
    const uint32_t st2 = data + 2 * STAGE_BYTES;

    load_chunk(0, st0);
    load_chunk(1, st1);

    // 27 chunks in 9 unrolled triples, then chunk 27 (stage 0).
#pragma unroll 1
    for (int cc = 0; cc < 27; cc += 3) {
        // step cc: stage 0, prefetch cc+2 -> stage 2
        cp_wait<1>(); __syncthreads();
        load_chunk(cc + 2, st2);
        compute(st0, (cc >= 4 && cc < 20));
        // step cc+1: stage 1, prefetch cc+3 -> stage 0
        cp_wait<1>(); __syncthreads();
        if (cc + 3 < NCH) load_chunk(cc + 3, st0);
        compute(st1, (cc + 1 >= 4 && cc + 1 < 20));
        // step cc+2: stage 2, prefetch cc+4 -> stage 1
        cp_wait<1>(); __syncthreads();
        if (cc + 4 < NCH) load_chunk(cc + 4, st1);
        compute(st2, (cc + 2 >= 4 && cc + 2 < 20));
    }
    // chunk 27, stage 0
    cp_wait<0>(); __syncthreads();
    compute(st0, false);

    // ---- fused epilogue (warp tile 32x16) ----
    const int g  = lane >> 2;
    const int c2 = (lane & 3) * 2;
#pragma unroll
    for (int mb = 0; mb < 2; ++mb)
#pragma unroll
        for (int nb = 0; nb < 2; ++nb) {
            const int n = n0 + wn + nb * 8 + c2;
            const float bg0 = __ldg(&b_gd[n]),        bg1 = __ldg(&b_gd[n + 1]);
            const float bd0 = __ldg(&b_gd[n + HID]),  bd1 = __ldg(&b_gd[n + HID + 1]);
            const float bt0 = __ldg(&b_tau[n]),       bt1 = __ldg(&b_tau[n + 1]);
            const float dc0 = softplus_f(__ldg(&cm[n]))   + softplus_f(__ldg(&gleak[n]))   + 1e-6f;
            const float dc1 = softplus_f(__ldg(&cm[n+1])) + softplus_f(__ldg(&gleak[n+1])) + 1e-6f;
#pragma unroll
            for (int h = 0; h < 2; ++h) {
                const int m = m0 + wm + mb * 16 + h * 8 + g;
                const float hl0 = __ldg(&h_ltc[(size_t)m * HID + n]);
                const float hl1 = __ldg(&h_ltc[(size_t)m * HID + n + 1]);

                float gate0 = accg[mb][nb][h * 2 + 0] + bg0;
                float gate1 = accg[mb][nb][h * 2 + 1] + bg1;
                float dyn0  = accd[mb][nb][h * 2 + 0] + bd0;
                float dyn1  = accd[mb][nb][h * 2 + 1] + bd1;
                float tau0  = softplus_f(acct[mb][nb][h * 2 + 0] + bt0);
                float tau1  = softplus_f(acct[mb][nb][h * 2 + 1] + bt1);

                float sig0 = 1.0f / (1.0f + expf(-gate0));
                float sig1 = 1.0f / (1.0f + expf(-gate1));
                float r0 = (sig0 * tanhf(dyn0) - hl0) / (tau0 + dc0);
                float r1 = (sig1 * tanhf(dyn1) - hl1) / (tau1 + dc1);

                float2 o; o.x = r0; o.y = r1;
                *reinterpret_cast<float2*>(&out[(size_t)m * HID + n]) = o;
            }
        }
}

extern "C" void kernel_launch(void* const* d_in, const int* in_sizes, int n_in,
                              void* d_out, int out_size)
{
    // input order: t, h_ltc, x_t, context, W_gd, b_gd, W_tau, b_tau, gleak, cm
    const float* h_ltc   = (const float*)d_in[1];
    const float* x_t     = (const float*)d_in[2];
    const float* context = (const float*)d_in[3];
    const float* W_gd    = (const float*)d_in[4];
    const float* b_gd    = (const float*)d_in[5];
    const float* W_tau   = (const float*)d_in[6];
    const float* b_tau   = (const float*)d_in[7];
    const float* gleak   = (const float*)d_in[8];
    const float* cm      = (const float*)d_in[9];
    float* out = (float*)d_out;

    cudaFuncSetAttribute(ltc_f16_kernel,
                         cudaFuncAttributeMaxDynamicSharedMemorySize, SMEM_DYN);

    prep_all<<<15488, 256>>>(h_ltc, x_t, context, W_gd, W_tau);

    dim3 grid(HID / BN, BROWS / BM);   // (8, 128)
    ltc_f16_kernel<<<grid, NTH, SMEM_DYN>>>(h_ltc, b_gd, b_tau, gleak, cm, out);
}

// round 10
// speedup vs baseline: 5.4702x; 1.1102x over previous
#include <cuda_runtime.h>
#include <cuda_fp16.h>
#include <math.h>
#include <stdint.h>

// LTCAttentionCell — round 10: R9 + KBLK=64 (14 chunks, 14 barriers instead of
// 28). 40KB stages x3, 16 warps, precomputed swizzled LDSM offsets, compile-time
// stage bases. fp16 single-term HMMA (engine frontier established R2-R7).

#define IN_DIM 128
#define HID    512
#define ATT    256
#define KTOT   896
#define BROWS  16384

#define BM 128
#define BN 64
#define KBLK 64
#define NCH (KTOT / KBLK)        // 14
#define NTH 512
#define STAGES 3
// stage: A 128 rows x 128B = 16K; Bg/Bd/Bt 64 rows x 128B = 8K each
#define A_SZ  16384
#define B_SZ  8192
#define STAGE_BYTES (A_SZ + 3 * B_SZ)            // 40960
#define SMEM_DYN (STAGES * STAGE_BYTES + 128)    // ~123K

__device__ __half g_comb[(size_t)BROWS * KTOT];
__device__ __half g_wgd [(size_t)1024  * KTOT];
__device__ __half g_wtau[(size_t)512   * HID];

__device__ __forceinline__ uint32_t s2u(const void* p) {
    return (uint32_t)__cvta_generic_to_shared(p);
}
__device__ __forceinline__ void cp16(uint32_t dst, const void* src) {
    asm volatile("cp.async.cg.shared.global [%0], [%1], 16;" :: "r"(dst), "l"(src));
}
__device__ __forceinline__ void cp_commit() {
    asm volatile("cp.async.commit_group;" ::: "memory");
}
template<int N> __device__ __forceinline__ void cp_wait() {
    asm volatile("cp.async.wait_group %0;" :: "n"(N) : "memory");
}
__device__ __forceinline__ void ldm_x4(uint32_t* d, uint32_t addr) {
    asm volatile("ldmatrix.sync.aligned.m8n8.x4.shared.b16 {%0,%1,%2,%3}, [%4];"
                 : "=r"(d[0]), "=r"(d[1]), "=r"(d[2]), "=r"(d[3]) : "r"(addr));
}
__device__ __forceinline__ void mma_f16(float* c, const uint32_t* a, uint32_t b0, uint32_t b1) {
    asm volatile("mma.sync.aligned.m16n8k16.row.col.f32.f16.f16.f32 "
                 "{%0,%1,%2,%3}, {%4,%5,%6,%7}, {%8,%9}, {%0,%1,%2,%3};"
                 : "+f"(c[0]), "+f"(c[1]), "+f"(c[2]), "+f"(c[3])
                 : "r"(a[0]), "r"(a[1]), "r"(a[2]), "r"(a[3]), "r"(b0), "r"(b1));
}
__device__ __forceinline__ float softplus_f(float x) {
    return (x > 20.0f) ? x : log1pf(expf(x));
}

// 128B rows = 8x16B chunks, SW128 swizzle: ch ^ (row & 7)
__device__ __forceinline__ uint32_t sw128(int row, int k) {
    int ch = k >> 3;
    return row * 128 + (((ch ^ (row & 7)) << 4) | ((k & 7) * 2));
}

// ---------------- fused pre-pass ----------------
__global__ void __launch_bounds__(256)
prep_all(const float* __restrict__ h_ltc, const float* __restrict__ x_t,
         const float* __restrict__ context, const float* __restrict__ W_gd,
         const float* __restrict__ W_tau)
{
    const float* src;
    __half* dst;
    if (blockIdx.x < 14336) {
        int idx = blockIdx.x * 256 + threadIdx.x;   // 16384 * 224
        int m = idx / 224;
        int j = (idx - m * 224) * 4;
        if (j < IN_DIM)            src = x_t     + (size_t)m * IN_DIM + j;
        else if (j < IN_DIM + HID) src = h_ltc   + (size_t)m * HID    + (j - IN_DIM);
        else                       src = context + (size_t)m * ATT    + (j - IN_DIM - HID);
        dst = &g_comb[(size_t)m * KTOT + j];
    } else {
        int idx = (blockIdx.x - 14336) * 256 + threadIdx.x;  // 229376 + 65536
        if (idx < 229376) {
            int row = idx / 224;
            int j = (idx - row * 224) * 4;
            src = &W_gd[(size_t)row * KTOT + j];
            dst = &g_wgd[(size_t)row * KTOT + j];
        } else {
            int e = idx - 229376;
            int row = e >> 7;
            int j = (e & 127) * 4;
            src = &W_tau[(size_t)row * HID + j];
            dst = &g_wtau[(size_t)row * HID + j];
        }
    }
    float4 v = *reinterpret_cast<const float4*>(src);
    __half2 p0, p1;
    p0.x = __float2half_rn(v.x); p0.y = __float2half_rn(v.y);
    p1.x = __float2half_rn(v.z); p1.y = __float2half_rn(v.w);
    *reinterpret_cast<__half2*>(dst + 0) = p0;
    *reinterpret_cast<__half2*>(dst + 2) = p1;
}

// ---------------- main kernel ----------------
__global__ void __launch_bounds__(NTH, 1)
ltc_f16_kernel(const float* __restrict__ h_ltc, const float* __restrict__ b_gd,
               const float* __restrict__ b_tau, const float* __restrict__ gleak,
               const float* __restrict__ cm, float* __restrict__ out)
{
    extern __shared__ char smem[];
    const uint32_t data = (s2u(smem) + 127) & ~127u;

    const int tid  = threadIdx.x;
    const int wid  = tid >> 5;
    const int lane = tid & 31;
    const int m0 = blockIdx.y * BM;
    const int n0 = blockIdx.x * BN;

    const int wm = (wid & 3) * 32;    // 4 m-warps x 4 n-warps, warp tile 32x16
    const int wn = (wid >> 2) * 16;

    const int a_row = ((lane >> 3) & 1) * 8 + (lane & 7);
    const int a_k   = ((lane >> 4) & 1) * 8;
    const int b_row = ((lane >> 4) & 1) * 8 + (lane & 7);
    const int b_k   = ((lane >> 3) & 1) * 8;

    // -------- precomputed stage-relative LDSM offsets (4 ks steps) --------
    uint32_t aoff[2][4], bgof[4];
#pragma unroll
    for (int ks = 0; ks < 4; ++ks) {
#pragma unroll
        for (int mb = 0; mb < 2; ++mb)
            aoff[mb][ks] = sw128(wm + mb * 16 + a_row, ks * 16 + a_k);
        bgof[ks] = A_SZ + sw128(wn + b_row, ks * 16 + b_k);
    }

    // -------- loader addressing (precomputed) --------
    const int ar = tid >> 3, ach = tid & 7;       // A: rows ar, ar+64
    const uint32_t dA0 = sw128(ar, ach * 8);
    const uint32_t dA1 = sw128(ar + 64, ach * 8);
    const uint32_t dB  = sw128(ar, ach * 8);      // B rows: same decode, 0..63
    const __half* srcA0 = g_comb + (size_t)(m0 + ar) * KTOT + ach * 8;
    const __half* srcA1 = g_comb + (size_t)(m0 + ar + 64) * KTOT + ach * 8;
    const __half* srcG  = g_wgd  + (size_t)(n0 + ar) * KTOT + ach * 8;        // ar<64 rows
    const __half* srcD  = g_wgd  + (size_t)(HID + n0 + ar) * KTOT + ach * 8;
    const __half* srcT  = g_wtau + (size_t)(n0 + ar) * HID + ach * 8;

    float accg[2][2][4] = {}, accd[2][2][4] = {}, acct[2][2][4] = {};

    auto load_chunk = [&](int c, uint32_t st) {
        cp16(st + dA0, srcA0 + c * 64);
        cp16(st + dA1, srcA1 + c * 64);
        cp16(st + A_SZ + dB,          srcG + c * 64);
        cp16(st + A_SZ + B_SZ + dB,   srcD + c * 64);
        if (c >= 2 && c < 10)
            cp16(st + A_SZ + 2 * B_SZ + dB, srcT + (c - 2) * 64);
        cp_commit();
    };

    auto compute = [&](uint32_t st, bool tau_act) {
#pragma unroll
        for (int ks = 0; ks < 4; ++ks) {
            uint32_t a[2][4];
            ldm_x4(a[0], st + aoff[0][ks]);
            ldm_x4(a[1], st + aoff[1][ks]);
            uint32_t bg[4], bd[4], bt[4];
            uint32_t bga = st + bgof[ks];
            ldm_x4(bg, bga);
            ldm_x4(bd, bga + B_SZ);
            if (tau_act) ldm_x4(bt, bga + 2 * B_SZ);
#pragma unroll
            for (int mb = 0; mb < 2; ++mb)
#pragma unroll
                for (int nb = 0; nb < 2; ++nb) {
                    mma_f16(accg[mb][nb], a[mb], bg[nb * 2], bg[nb * 2 + 1]);
                    mma_f16(accd[mb][nb], a[mb], bd[nb * 2], bd[nb * 2 + 1]);
                }
            if (tau_act) {
#pragma unroll
                for (int mb = 0; mb < 2; ++mb)
#pragma unroll
                    for (int nb = 0; nb < 2; ++nb)
                        mma_f16(acct[mb][nb], a[mb], bt[nb * 2], bt[nb * 2 + 1]);
            }
        }
    };

    const uint32_t st0 = data;
    const uint32_t st1 = data + STAGE_BYTES;
    const uint32_t st2 = data + 2 * STAGE_BYTES;

    load_chunk(0, st0);
    load_chunk(1, st1);

    // tau chunks: c in [2, 10)
#pragma unroll 1
    for (int cc = 0; cc < 12; cc += 3) {
        cp_wait<1>(); __syncthreads();
        load_chunk(cc + 2, st2);
        compute(st0, (cc >= 2 && cc < 10));

        cp_wait<1>(); __syncthreads();
        load_chunk(cc + 3, st0);
        compute(st1, (cc + 1 >= 2 && cc + 1 < 10));

        cp_wait<1>(); __syncthreads();
        if (cc + 4 < NCH) load_chunk(cc + 4, st1);
        compute(st2, (cc + 2 >= 2 && cc + 2 < 10));
    }
    // chunk 12 (stage 0): only load(13) pending
    cp_wait<1>(); __syncthreads();
    compute(st0, false);
    // chunk 13 (stage 1)
    cp_wait<0>(); __syncthreads();
    compute(st1, false);

    // ---- fused epilogue (warp tile 32x16) ----
    const int g  = lane >> 2;
    const int c2 = (lane & 3) * 2;
#pragma unroll
    for (int mb = 0; mb < 2; ++mb)
#pragma unroll
        for (int nb = 0; nb < 2; ++nb) {
            const int n = n0 + wn + nb * 8 + c2;
            const float bg0 = __ldg(&b_gd[n]),        bg1 = __ldg(&b_gd[n + 1]);
            const float bd0 = __ldg(&b_gd[n + HID]),  bd1 = __ldg(&b_gd[n + HID + 1]);
            const float bt0 = __ldg(&b_tau[n]),       bt1 = __ldg(&b_tau[n + 1]);
            const float dc0 = softplus_f(__ldg(&cm[n]))   + softplus_f(__ldg(&gleak[n]))   + 1e-6f;
            const float dc1 = softplus_f(__ldg(&cm[n+1])) + softplus_f(__ldg(&gleak[n+1])) + 1e-6f;
#pragma unroll
            for (int h = 0; h < 2; ++h) {
                const int m = m0 + wm + mb * 16 + h * 8 + g;
                const float hl0 = __ldg(&h_ltc[(size_t)m * HID + n]);
                const float hl1 = __ldg(&h_ltc[(size_t)m * HID + n + 1]);

                float gate0 = accg[mb][nb][h * 2 + 0] + bg0;
                float gate1 = accg[mb][nb][h * 2 + 1] + bg1;
                float dyn0  = accd[mb][nb][h * 2 + 0] + bd0;
                float dyn1  = accd[mb][nb][h * 2 + 1] + bd1;
                float tau0  = softplus_f(acct[mb][nb][h * 2 + 0] + bt0);
                float tau1  = softplus_f(acct[mb][nb][h * 2 + 1] + bt1);

                float sig0 = 1.0f / (1.0f + expf(-gate0));
                float sig1 = 1.0f / (1.0f + expf(-gate1));
                float r0 = (sig0 * tanhf(dyn0) - hl0) / (tau0 + dc0);
                float r1 = (sig1 * tanhf(dyn1) - hl1) / (tau1 + dc1);

                float2 o; o.x = r0; o.y = r1;
                *reinterpret_cast<float2*>(&out[(size_t)m * HID + n]) = o;
            }
        }
}

extern "C" void kernel_launch(void* const* d_in, const int* in_sizes, int n_in,
                              void* d_out, int out_size)
{
    // input order: t, h_ltc, x_t, context, W_gd, b_gd, W_tau, b_tau, gleak, cm
    const float* h_ltc   = (const float*)d_in[1];
    const float* x_t     = (const float*)d_in[2];
    const float* context = (const float*)d_in[3];
    const float* W_gd    = (const float*)d_in[4];
    const float* b_gd    = (const float*)d_in[5];
    const float* W_tau   = (const float*)d_in[6];
    const float* b_tau   = (const float*)d_in[7];
    const float* gleak   = (const float*)d_in[8];
    const float* cm      = (const float*)d_in[9];
    float* out = (float*)d_out;

    cudaFuncSetAttribute(ltc_f16_kernel,
                         cudaFuncAttributeMaxDynamicSharedMemorySize, SMEM_DYN);

    prep_all<<<15488, 256>>>(h_ltc, x_t, context, W_gd, W_tau);

    dim3 grid(HID / BN, BROWS / BM);   // (8, 128)
    ltc_f16_kernel<<<grid, NTH, SMEM_DYN>>>(h_ltc, b_gd, b_tau, gleak, cm, out);
}

// round 11
// speedup vs baseline: 5.9338x; 1.0847x over previous
#include <cuda_runtime.h>
#include <cuda_fp16.h>
#include <math.h>
#include <stdint.h>

// LTCAttentionCell — round 11: KBLK=128 (7 chunks / 7 barriers, measured barrier
// cost ~1.3us each), 2-stage 160KB pipeline, 256B rows with SW swizzle
// ((ch&7)^(row&7))|(ch&8) so ks+4 LDSM addr = ks addr + 128B. Prep: 8 elem/thread.

#define IN_DIM 128
#define HID    512
#define ATT    256
#define KTOT   896
#define BROWS  16384

#define BM 128
#define BN 64
#define KBLK 128
#define NCH (KTOT / KBLK)        // 7
#define NTH 512
#define A_SZ  32768              // 128 rows x 256B
#define B_SZ  16384              // 64 rows x 256B
#define STAGE_BYTES (A_SZ + 3 * B_SZ)        // 81920
#define SMEM_DYN (2 * STAGE_BYTES + 128)     // ~160K

__device__ __half g_comb[(size_t)BROWS * KTOT];
__device__ __half g_wgd [(size_t)1024  * KTOT];
__device__ __half g_wtau[(size_t)512   * HID];

__device__ __forceinline__ uint32_t s2u(const void* p) {
    return (uint32_t)__cvta_generic_to_shared(p);
}
__device__ __forceinline__ void cp16(uint32_t dst, const void* src) {
    asm volatile("cp.async.cg.shared.global [%0], [%1], 16;" :: "r"(dst), "l"(src));
}
__device__ __forceinline__ void cp_commit() {
    asm volatile("cp.async.commit_group;" ::: "memory");
}
template<int N> __device__ __forceinline__ void cp_wait() {
    asm volatile("cp.async.wait_group %0;" :: "n"(N) : "memory");
}
__device__ __forceinline__ void ldm_x4(uint32_t* d, uint32_t addr) {
    asm volatile("ldmatrix.sync.aligned.m8n8.x4.shared.b16 {%0,%1,%2,%3}, [%4];"
                 : "=r"(d[0]), "=r"(d[1]), "=r"(d[2]), "=r"(d[3]) : "r"(addr));
}
__device__ __forceinline__ void mma_f16(float* c, const uint32_t* a, uint32_t b0, uint32_t b1) {
    asm volatile("mma.sync.aligned.m16n8k16.row.col.f32.f16.f16.f32 "
                 "{%0,%1,%2,%3}, {%4,%5,%6,%7}, {%8,%9}, {%0,%1,%2,%3};"
                 : "+f"(c[0]), "+f"(c[1]), "+f"(c[2]), "+f"(c[3])
                 : "r"(a[0]), "r"(a[1]), "r"(a[2]), "r"(a[3]), "r"(b0), "r"(b1));
}
__device__ __forceinline__ float softplus_f(float x) {
    return (x > 20.0f) ? x : log1pf(expf(x));
}

// 256B rows = 16x16B chunks; swizzle low 3 bits of chunk with row&7
__device__ __forceinline__ uint32_t sw256(int row, int k) {
    int ch = k >> 3;
    int swc = ((ch & 7) ^ (row & 7)) | (ch & 8);
    return row * 256 + ((swc << 4) | ((k & 7) * 2));
}

// ---------------- fused pre-pass: 8 elems/thread ----------------
__device__ __forceinline__ void cvt8(const float* src, __half* dst) {
    float4 v0 = *reinterpret_cast<const float4*>(src);
    float4 v1 = *reinterpret_cast<const float4*>(src + 4);
    __half2 h0, h1, h2, h3;
    h0.x = __float2half_rn(v0.x); h0.y = __float2half_rn(v0.y);
    h1.x = __float2half_rn(v0.z); h1.y = __float2half_rn(v0.w);
    h2.x = __float2half_rn(v1.x); h2.y = __float2half_rn(v1.y);
    h3.x = __float2half_rn(v1.z); h3.y = __float2half_rn(v1.w);
    uint4 o;
    o.x = *reinterpret_cast<uint32_t*>(&h0);
    o.y = *reinterpret_cast<uint32_t*>(&h1);
    o.z = *reinterpret_cast<uint32_t*>(&h2);
    o.w = *reinterpret_cast<uint32_t*>(&h3);
    *reinterpret_cast<uint4*>(dst) = o;
}

__global__ void __launch_bounds__(256)
prep_all(const float* __restrict__ h_ltc, const float* __restrict__ x_t,
         const float* __restrict__ context, const float* __restrict__ W_gd,
         const float* __restrict__ W_tau)
{
    if (blockIdx.x < 7168) {
        int idx = blockIdx.x * 256 + threadIdx.x;   // 16384 * 112
        int m = idx / 112;
        int j = (idx - m * 112) * 8;
        const float* src;
        if (j < IN_DIM)            src = x_t     + (size_t)m * IN_DIM + j;
        else if (j < IN_DIM + HID) src = h_ltc   + (size_t)m * HID    + (j - IN_DIM);
        else                       src = context + (size_t)m * ATT    + (j - IN_DIM - HID);
        cvt8(src, &g_comb[(size_t)m * KTOT + j]);
    } else {
        int idx = (blockIdx.x - 7168) * 256 + threadIdx.x;  // 114688 + 32768
        if (idx < 114688) {
            int row = idx / 112;
            int j = (idx - row * 112) * 8;
            cvt8(&W_gd[(size_t)row * KTOT + j], &g_wgd[(size_t)row * KTOT + j]);
        } else {
            int e = idx - 114688;
            int row = e >> 6;
            int j = (e & 63) * 8;
            cvt8(&W_tau[(size_t)row * HID + j], &g_wtau[(size_t)row * HID + j]);
        }
    }
}

// ---------------- main kernel ----------------
__global__ void __launch_bounds__(NTH, 1)
ltc_f16_kernel(const float* __restrict__ h_ltc, const float* __restrict__ b_gd,
               const float* __restrict__ b_tau, const float* __restrict__ gleak,
               const float* __restrict__ cm, float* __restrict__ out)
{
    extern __shared__ char smem[];
    const uint32_t data = (s2u(smem) + 127) & ~127u;

    const int tid  = threadIdx.x;
    const int wid  = tid >> 5;
    const int lane = tid & 31;
    const int m0 = blockIdx.y * BM;
    const int n0 = blockIdx.x * BN;

    const int wm = (wid & 3) * 32;    // 4 m-warps x 4 n-warps, warp tile 32x16
    const int wn = (wid >> 2) * 16;

    const int a_row = ((lane >> 3) & 1) * 8 + (lane & 7);
    const int a_k   = ((lane >> 4) & 1) * 8;
    const int b_row = ((lane >> 4) & 1) * 8 + (lane & 7);
    const int b_k   = ((lane >> 3) & 1) * 8;

    // LDSM offsets for ks 0..3; ks+4 = +128 bytes (ch bit 3 unswizzled)
    uint32_t aoff[2][4], bgof[4];
#pragma unroll
    for (int ks = 0; ks < 4; ++ks) {
#pragma unroll
        for (int mb = 0; mb < 2; ++mb)
            aoff[mb][ks] = sw256(wm + mb * 16 + a_row, ks * 16 + a_k);
        bgof[ks] = A_SZ + sw256(wn + b_row, ks * 16 + b_k);
    }

    // loader addressing: A 128 rows x 16 ch = 2048 slots (4/thread),
    // B 64 rows x 16 ch = 1024 slots (2/thread/matrix)
    uint32_t dAo[4]; const __half* srcA[4];
#pragma unroll
    for (int i = 0; i < 4; ++i) {
        int s = tid + i * 512, r = s >> 4, ch = s & 15;
        dAo[i] = sw256(r, ch * 8);
        srcA[i] = g_comb + (size_t)(m0 + r) * KTOT + ch * 8;
    }
    uint32_t dBo[2]; const __half *srcG[2], *srcD[2], *srcT[2];
#pragma unroll
    for (int i = 0; i < 2; ++i) {
        int s = tid + i * 512, r = s >> 4, ch = s & 15;
        dBo[i] = sw256(r, ch * 8);
        srcG[i] = g_wgd  + (size_t)(n0 + r) * KTOT + ch * 8;
        srcD[i] = g_wgd  + (size_t)(HID + n0 + r) * KTOT + ch * 8;
        srcT[i] = g_wtau + (size_t)(n0 + r) * HID + ch * 8;
    }

    float accg[2][2][4] = {}, accd[2][2][4] = {}, acct[2][2][4] = {};

    auto load_chunk = [&](int c, uint32_t st) {
#pragma unroll
        for (int i = 0; i < 4; ++i)
            cp16(st + dAo[i], srcA[i] + c * KBLK);
#pragma unroll
        for (int i = 0; i < 2; ++i) {
            cp16(st + A_SZ + dBo[i],        srcG[i] + c * KBLK);
            cp16(st + A_SZ + B_SZ + dBo[i], srcD[i] + c * KBLK);
        }
        if (c >= 1 && c < 5) {
#pragma unroll
            for (int i = 0; i < 2; ++i)
                cp16(st + A_SZ + 2 * B_SZ + dBo[i], srcT[i] + (c - 1) * KBLK);
        }
        cp_commit();
    };

    auto compute = [&](uint32_t st, bool tau_act) {
#pragma unroll
        for (int k8 = 0; k8 < 8; ++k8) {
            const int ks = k8 & 3;
            const uint32_t ext = (k8 >> 2) * 128;
            uint32_t a[2][4];
            ldm_x4(a[0], st + aoff[0][ks] + ext);
            ldm_x4(a[1], st + aoff[1][ks] + ext);
            uint32_t bg[4], bd[4], bt[4];
            const uint32_t bga = st + bgof[ks] + ext;
            ldm_x4(bg, bga);
            ldm_x4(bd, bga + B_SZ);
            if (tau_act) ldm_x4(bt, bga + 2 * B_SZ);
#pragma unroll
            for (int mb = 0; mb < 2; ++mb)
#pragma unroll
                for (int nb = 0; nb < 2; ++nb) {
                    mma_f16(accg[mb][nb], a[mb], bg[nb * 2], bg[nb * 2 + 1]);
                    mma_f16(accd[mb][nb], a[mb], bd[nb * 2], bd[nb * 2 + 1]);
                }
            if (tau_act) {
#pragma unroll
                for (int mb = 0; mb < 2; ++mb)
#pragma unroll
                    for (int nb = 0; nb < 2; ++nb)
                        mma_f16(acct[mb][nb], a[mb], bt[nb * 2], bt[nb * 2 + 1]);
            }
        }
    };

    const uint32_t st0 = data;
    const uint32_t st1 = data + STAGE_BYTES;

    // chunks: c=0 (x_t part), c=1..4 (tau active), c=5,6. stage = c&1.
    load_chunk(0, st0);

    cp_wait<0>(); __syncthreads();
    load_chunk(1, st1);
    compute(st0, false);          // c=0

    cp_wait<0>(); __syncthreads();
    load_chunk(2, st0);
    compute(st1, true);           // c=1

    cp_wait<0>(); __syncthreads();
    load_chunk(3, st1);
    compute(st0, true);           // c=2

    cp_wait<0>(); __syncthreads();
    load_chunk(4, st0);
    compute(st1, true);           // c=3

    cp_wait<0>(); __syncthreads();
    load_chunk(5, st1);
    compute(st0, true);           // c=4

    cp_wait<0>(); __syncthreads();
    load_chunk(6, st0);
    compute(st1, false);          // c=5

    cp_wait<0>(); __syncthreads();
    compute(st0, false);          // c=6

    // ---- fused epilogue (warp tile 32x16) ----
    const int g  = lane >> 2;
    const int c2 = (lane & 3) * 2;
#pragma unroll
    for (int mb = 0; mb < 2; ++mb)
#pragma unroll
        for (int nb = 0; nb < 2; ++nb) {
            const int n = n0 + wn + nb * 8 + c2;
            const float bg0 = __ldg(&b_gd[n]),        bg1 = __ldg(&b_gd[n + 1]);
            const float bd0 = __ldg(&b_gd[n + HID]),  bd1 = __ldg(&b_gd[n + HID + 1]);
            const float bt0 = __ldg(&b_tau[n]),       bt1 = __ldg(&b_tau[n + 1]);
            const float dc0 = softplus_f(__ldg(&cm[n]))   + softplus_f(__ldg(&gleak[n]))   + 1e-6f;
            const float dc1 = softplus_f(__ldg(&cm[n+1])) + softplus_f(__ldg(&gleak[n+1])) + 1e-6f;
#pragma unroll
            for (int h = 0; h < 2; ++h) {
                const int m = m0 + wm + mb * 16 + h * 8 + g;
                const float hl0 = __ldg(&h_ltc[(size_t)m * HID + n]);
                const float hl1 = __ldg(&h_ltc[(size_t)m * HID + n + 1]);

                float gate0 = accg[mb][nb][h * 2 + 0] + bg0;
                float gate1 = accg[mb][nb][h * 2 + 1] + bg1;
                float dyn0  = accd[mb][nb][h * 2 + 0] + bd0;
                float dyn1  = accd[mb][nb][h * 2 + 1] + bd1;
                float tau0  = softplus_f(acct[mb][nb][h * 2 + 0] + bt0);
                float tau1  = softplus_f(acct[mb][nb][h * 2 + 1] + bt1);

                float sig0 = 1.0f / (1.0f + expf(-gate0));
                float sig1 = 1.0f / (1.0f + expf(-gate1));
                float r0 = (sig0 * tanhf(dyn0) - hl0) / (tau0 + dc0);
                float r1 = (sig1 * tanhf(dyn1) - hl1) / (tau1 + dc1);

                float2 o; o.x = r0; o.y = r1;
                *reinterpret_cast<float2*>(&out[(size_t)m * HID + n]) = o;
            }
        }
}

extern "C" void kernel_launch(void* const* d_in, const int* in_sizes, int n_in,
                              void* d_out, int out_size)
{
    // input order: t, h_ltc, x_t, context, W_gd, b_gd, W_tau, b_tau, gleak, cm
    const float* h_ltc   = (const float*)d_in[1];
    const float* x_t     = (const float*)d_in[2];
    const float* context = (const float*)d_in[3];
    const float* W_gd    = (const float*)d_in[4];
    const float* b_gd    = (const float*)d_in[5];
    const float* W_tau   = (const float*)d_in[6];
    const float* b_tau   = (const float*)d_in[7];
    const float* gleak   = (const float*)d_in[8];
    const float* cm      = (const float*)d_in[9];
    float* out = (float*)d_out;

    cudaFuncSetAttribute(ltc_f16_kernel,
                         cudaFuncAttributeMaxDynamicSharedMemorySize, SMEM_DYN);

    prep_all<<<7744, 256>>>(h_ltc, x_t, context, W_gd, W_tau);

    dim3 grid(HID / BN, BROWS / BM);   // (8, 128)
    ltc_f16_kernel<<<grid, NTH, SMEM_DYN>>>(h_ltc, b_gd, b_tau, gleak, cm, out);
}

// round 12
// speedup vs baseline: 6.5262x; 1.0998x over previous
#include <cuda_runtime.h>
#include <cuda_fp16.h>
#include <math.h>
#include <stdint.h>

// LTCAttentionCell — round 12: R11 (KBLK=128, 7 barriers, 2-stage, 16 warps)
// + fast-math epilogue (__expf/__logf/__fdividef). Epilogue was ~15us of
// libm sequences; intrinsic error ~1e-6 << 1.7e-4 fp16 quantization floor.

#define IN_DIM 128
#define HID    512
#define ATT    256
#define KTOT   896
#define BROWS  16384

#define BM 128
#define BN 64
#define KBLK 128
#define NCH (KTOT / KBLK)        // 7
#define NTH 512
#define A_SZ  32768              // 128 rows x 256B
#define B_SZ  16384              // 64 rows x 256B
#define STAGE_BYTES (A_SZ + 3 * B_SZ)        // 81920
#define SMEM_DYN (2 * STAGE_BYTES + 128)     // ~160K

__device__ __half g_comb[(size_t)BROWS * KTOT];
__device__ __half g_wgd [(size_t)1024  * KTOT];
__device__ __half g_wtau[(size_t)512   * HID];

__device__ __forceinline__ uint32_t s2u(const void* p) {
    return (uint32_t)__cvta_generic_to_shared(p);
}
__device__ __forceinline__ void cp16(uint32_t dst, const void* src) {
    asm volatile("cp.async.cg.shared.global [%0], [%1], 16;" :: "r"(dst), "l"(src));
}
__device__ __forceinline__ void cp_commit() {
    asm volatile("cp.async.commit_group;" ::: "memory");
}
template<int N> __device__ __forceinline__ void cp_wait() {
    asm volatile("cp.async.wait_group %0;" :: "n"(N) : "memory");
}
__device__ __forceinline__ void ldm_x4(uint32_t* d, uint32_t addr) {
    asm volatile("ldmatrix.sync.aligned.m8n8.x4.shared.b16 {%0,%1,%2,%3}, [%4];"
                 : "=r"(d[0]), "=r"(d[1]), "=r"(d[2]), "=r"(d[3]) : "r"(addr));
}
__device__ __forceinline__ void mma_f16(float* c, const uint32_t* a, uint32_t b0, uint32_t b1) {
    asm volatile("mma.sync.aligned.m16n8k16.row.col.f32.f16.f16.f32 "
                 "{%0,%1,%2,%3}, {%4,%5,%6,%7}, {%8,%9}, {%0,%1,%2,%3};"
                 : "+f"(c[0]), "+f"(c[1]), "+f"(c[2]), "+f"(c[3])
                 : "r"(a[0]), "r"(a[1]), "r"(a[2]), "r"(a[3]), "r"(b0), "r"(b1));
}

// ---- fast-math activation helpers (err ~1e-6 << 1.7e-4 fp16 floor) ----
__device__ __forceinline__ float softplus_fast(float x) {
    return (x > 20.0f) ? x : __logf(1.0f + __expf(x));
}
__device__ __forceinline__ float sigmoid_fast(float x) {
    return __fdividef(1.0f, 1.0f + __expf(-x));
}
__device__ __forceinline__ float tanh_fast(float x) {
    // 1 - 2/(e^{2x}+1); exact limits at +/-inf
    return 1.0f - __fdividef(2.0f, __expf(2.0f * x) + 1.0f);
}

// 256B rows = 16x16B chunks; swizzle low 3 bits of chunk with row&7
__device__ __forceinline__ uint32_t sw256(int row, int k) {
    int ch = k >> 3;
    int swc = ((ch & 7) ^ (row & 7)) | (ch & 8);
    return row * 256 + ((swc << 4) | ((k & 7) * 2));
}

// ---------------- fused pre-pass: 8 elems/thread ----------------
__device__ __forceinline__ void cvt8(const float* src, __half* dst) {
    float4 v0 = *reinterpret_cast<const float4*>(src);
    float4 v1 = *reinterpret_cast<const float4*>(src + 4);
    __half2 h0, h1, h2, h3;
    h0.x = __float2half_rn(v0.x); h0.y = __float2half_rn(v0.y);
    h1.x = __float2half_rn(v0.z); h1.y = __float2half_rn(v0.w);
    h2.x = __float2half_rn(v1.x); h2.y = __float2half_rn(v1.y);
    h3.x = __float2half_rn(v1.z); h3.y = __float2half_rn(v1.w);
    uint4 o;
    o.x = *reinterpret_cast<uint32_t*>(&h0);
    o.y = *reinterpret_cast<uint32_t*>(&h1);
    o.z = *reinterpret_cast<uint32_t*>(&h2);
    o.w = *reinterpret_cast<uint32_t*>(&h3);
    *reinterpret_cast<uint4*>(dst) = o;
}

__global__ void __launch_bounds__(256)
prep_all(const float* __restrict__ h_ltc, const float* __restrict__ x_t,
         const float* __restrict__ context, const float* __restrict__ W_gd,
         const float* __restrict__ W_tau)
{
    if (blockIdx.x < 7168) {
        int idx = blockIdx.x * 256 + threadIdx.x;   // 16384 * 112
        int m = idx / 112;
        int j = (idx - m * 112) * 8;
        const float* src;
        if (j < IN_DIM)            src = x_t     + (size_t)m * IN_DIM + j;
        else if (j < IN_DIM + HID) src = h_ltc   + (size_t)m * HID    + (j - IN_DIM);
        else                       src = context + (size_t)m * ATT    + (j - IN_DIM - HID);
        cvt8(src, &g_comb[(size_t)m * KTOT + j]);
    } else {
        int idx = (blockIdx.x - 7168) * 256 + threadIdx.x;  // 114688 + 32768
        if (idx < 114688) {
            int row = idx / 112;
            int j = (idx - row * 112) * 8;
            cvt8(&W_gd[(size_t)row * KTOT + j], &g_wgd[(size_t)row * KTOT + j]);
        } else {
            int e = idx - 114688;
            int row = e >> 6;
            int j = (e & 63) * 8;
            cvt8(&W_tau[(size_t)row * HID + j], &g_wtau[(size_t)row * HID + j]);
        }
    }
}

// ---------------- main kernel ----------------
__global__ void __launch_bounds__(NTH, 1)
ltc_f16_kernel(const float* __restrict__ h_ltc, const float* __restrict__ b_gd,
               const float* __restrict__ b_tau, const float* __restrict__ gleak,
               const float* __restrict__ cm, float* __restrict__ out)
{
    extern __shared__ char smem[];
    const uint32_t data = (s2u(smem) + 127) & ~127u;

    const int tid  = threadIdx.x;
    const int wid  = tid >> 5;
    const int lane = tid & 31;
    const int m0 = blockIdx.y * BM;
    const int n0 = blockIdx.x * BN;

    const int wm = (wid & 3) * 32;    // 4 m-warps x 4 n-warps, warp tile 32x16
    const int wn = (wid >> 2) * 16;

    const int a_row = ((lane >> 3) & 1) * 8 + (lane & 7);
    const int a_k   = ((lane >> 4) & 1) * 8;
    const int b_row = ((lane >> 4) & 1) * 8 + (lane & 7);
    const int b_k   = ((lane >> 3) & 1) * 8;

    // LDSM offsets for ks 0..3; ks+4 = +128 bytes (ch bit 3 unswizzled)
    uint32_t aoff[2][4], bgof[4];
#pragma unroll
    for (int ks = 0; ks < 4; ++ks) {
#pragma unroll
        for (int mb = 0; mb < 2; ++mb)
            aoff[mb][ks] = sw256(wm + mb * 16 + a_row, ks * 16 + a_k);
        bgof[ks] = A_SZ + sw256(wn + b_row, ks * 16 + b_k);
    }

    // loader addressing: A 128 rows x 16 ch = 2048 slots (4/thread),
    // B 64 rows x 16 ch = 1024 slots (2/thread/matrix)
    uint32_t dAo[4]; const __half* srcA[4];
#pragma unroll
    for (int i = 0; i < 4; ++i) {
        int s = tid + i * 512, r = s >> 4, ch = s & 15;
        dAo[i] = sw256(r, ch * 8);
        srcA[i] = g_comb + (size_t)(m0 + r) * KTOT + ch * 8;
    }
    uint32_t dBo[2]; const __half *srcG[2], *srcD[2], *srcT[2];
#pragma unroll
    for (int i = 0; i < 2; ++i) {
        int s = tid + i * 512, r = s >> 4, ch = s & 15;
        dBo[i] = sw256(r, ch * 8);
        srcG[i] = g_wgd  + (size_t)(n0 + r) * KTOT + ch * 8;
        srcD[i] = g_wgd  + (size_t)(HID + n0 + r) * KTOT + ch * 8;
        srcT[i] = g_wtau + (size_t)(n0 + r) * HID + ch * 8;
    }

    float accg[2][2][4] = {}, accd[2][2][4] = {}, acct[2][2][4] = {};

    auto load_chunk = [&](int c, uint32_t st) {
#pragma unroll
        for (int i = 0; i < 4; ++i)
            cp16(st + dAo[i], srcA[i] + c * KBLK);
#pragma unroll
        for (int i = 0; i < 2; ++i) {
            cp16(st + A_SZ + dBo[i],        srcG[i] + c * KBLK);
            cp16(st + A_SZ + B_SZ + dBo[i], srcD[i] + c * KBLK);
        }
        if (c >= 1 && c < 5) {
#pragma unroll
            for (int i = 0; i < 2; ++i)
                cp16(st + A_SZ + 2 * B_SZ + dBo[i], srcT[i] + (c - 1) * KBLK);
        }
        cp_commit();
    };

    auto compute = [&](uint32_t st, bool tau_act) {
#pragma unroll
        for (int k8 = 0; k8 < 8; ++k8) {
            const int ks = k8 & 3;
            const uint32_t ext = (k8 >> 2) * 128;
            uint32_t a[2][4];
            ldm_x4(a[0], st + aoff[0][ks] + ext);
            ldm_x4(a[1], st + aoff[1][ks] + ext);
            uint32_t bg[4], bd[4], bt[4];
            const uint32_t bga = st + bgof[ks] + ext;
            ldm_x4(bg, bga);
            ldm_x4(bd, bga + B_SZ);
            if (tau_act) ldm_x4(bt, bga + 2 * B_SZ);
#pragma unroll
            for (int mb = 0; mb < 2; ++mb)
#pragma unroll
                for (int nb = 0; nb < 2; ++nb) {
                    mma_f16(accg[mb][nb], a[mb], bg[nb * 2], bg[nb * 2 + 1]);
                    mma_f16(accd[mb][nb], a[mb], bd[nb * 2], bd[nb * 2 + 1]);
                }
            if (tau_act) {
#pragma unroll
                for (int mb = 0; mb < 2; ++mb)
#pragma unroll
                    for (int nb = 0; nb < 2; ++nb)
                        mma_f16(acct[mb][nb], a[mb], bt[nb * 2], bt[nb * 2 + 1]);
            }
        }
    };

    const uint32_t st0 = data;
    const uint32_t st1 = data + STAGE_BYTES;

    // chunks: c=0, c=1..4 (tau active), c=5,6. stage = c&1.
    load_chunk(0, st0);

    cp_wait<0>(); __syncthreads();
    load_chunk(1, st1);
    compute(st0, false);          // c=0

    cp_wait<0>(); __syncthreads();
    load_chunk(2, st0);
    compute(st1, true);           // c=1

    cp_wait<0>(); __syncthreads();
    load_chunk(3, st1);
    compute(st0, true);           // c=2

    cp_wait<0>(); __syncthreads();
    load_chunk(4, st0);
    compute(st1, true);           // c=3

    cp_wait<0>(); __syncthreads();
    load_chunk(5, st1);
    compute(st0, true);           // c=4

    cp_wait<0>(); __syncthreads();
    load_chunk(6, st0);
    compute(st1, false);          // c=5

    cp_wait<0>(); __syncthreads();
    compute(st0, false);          // c=6

    // ---- fused epilogue (fast math) ----
    const int g  = lane >> 2;
    const int c2 = (lane & 3) * 2;
#pragma unroll
    for (int mb = 0; mb < 2; ++mb)
#pragma unroll
        for (int nb = 0; nb < 2; ++nb) {
            const int n = n0 + wn + nb * 8 + c2;
            const float bg0 = __ldg(&b_gd[n]),        bg1 = __ldg(&b_gd[n + 1]);
            const float bd0 = __ldg(&b_gd[n + HID]),  bd1 = __ldg(&b_gd[n + HID + 1]);
            const float bt0 = __ldg(&b_tau[n]),       bt1 = __ldg(&b_tau[n + 1]);
            const float dc0 = softplus_fast(__ldg(&cm[n]))   + softplus_fast(__ldg(&gleak[n]))   + 1e-6f;
            const float dc1 = softplus_fast(__ldg(&cm[n+1])) + softplus_fast(__ldg(&gleak[n+1])) + 1e-6f;
#pragma unroll
            for (int h = 0; h < 2; ++h) {
                const int m = m0 + wm + mb * 16 + h * 8 + g;
                const float2 hl = *reinterpret_cast<const float2*>(&h_ltc[(size_t)m * HID + n]);

                float gate0 = accg[mb][nb][h * 2 + 0] + bg0;
                float gate1 = accg[mb][nb][h * 2 + 1] + bg1;
                float dyn0  = accd[mb][nb][h * 2 + 0] + bd0;
                float dyn1  = accd[mb][nb][h * 2 + 1] + bd1;
                float tau0  = softplus_fast(acct[mb][nb][h * 2 + 0] + bt0);
                float tau1  = softplus_fast(acct[mb][nb][h * 2 + 1] + bt1);

                float r0 = __fdividef(sigmoid_fast(gate0) * tanh_fast(dyn0) - hl.x, tau0 + dc0);
                float r1 = __fdividef(sigmoid_fast(gate1) * tanh_fast(dyn1) - hl.y, tau1 + dc1);

                float2 o; o.x = r0; o.y = r1;
                *reinterpret_cast<float2*>(&out[(size_t)m * HID + n]) = o;
            }
        }
}

extern "C" void kernel_launch(void* const* d_in, const int* in_sizes, int n_in,
                              void* d_out, int out_size)
{
    // input order: t, h_ltc, x_t, context, W_gd, b_gd, W_tau, b_tau, gleak, cm
    const float* h_ltc   = (const float*)d_in[1];
    const float* x_t     = (const float*)d_in[2];
    const float* context = (const float*)d_in[3];
    const float* W_gd    = (const float*)d_in[4];
    const float* b_gd    = (const float*)d_in[5];
    const float* W_tau   = (const float*)d_in[6];
    const float* b_tau   = (const float*)d_in[7];
    const float* gleak   = (const float*)d_in[8];
    const float* cm      = (const float*)d_in[9];
    float* out = (float*)d_out;

    cudaFuncSetAttribute(ltc_f16_kernel,
                         cudaFuncAttributeMaxDynamicSharedMemorySize, SMEM_DYN);

    prep_all<<<7744, 256>>>(h_ltc, x_t, context, W_gd, W_tau);

    dim3 grid(HID / BN, BROWS / BM);   // (8, 128)
    ltc_f16_kernel<<<grid, NTH, SMEM_DYN>>>(h_ltc, b_gd, b_tau, gleak, cm, out);
}